// round 1
// baseline (speedup 1.0000x reference)
#include <cuda_runtime.h>
#include <cuda_bf16.h>
#include <math.h>

// ---------------- problem constants ----------------
#define CDIM 256
#define HEADS 8
#define DH 32
#define BATCH 8
#define QPER 128
#define KVPER 1024
#define NQ (BATCH*QPER)      // 1024
#define NKV (BATCH*KVPER)    // 8192
#define RMS_EPS 1.1920928955078125e-07f
#define ATTN_SCALE 0.17677669529663687f  // 1/sqrt(32)
#define NSPLIT 4             // cross-attn key splits

// ---------------- scratch (device globals; no cudaMalloc allowed) ----------
__device__ float g_kvn[NKV*CDIM];
__device__ float g_Kc [NKV*CDIM];
__device__ float g_Vc [NKV*CDIM];
__device__ float g_mh [NQ*CDIM];
__device__ float g_mk [NQ*CDIM];
__device__ float g_zT [BATCH*KVPER*QPER];   // per batch: [kv=1024][q=128]
__device__ float g_qn [NQ*CDIM];
__device__ float g_Qc [NQ*CDIM];
__device__ float g_attn[NQ*CDIM];
__device__ float g_q1 [NQ*CDIM];
__device__ float g_q2 [NQ*CDIM];
__device__ float g_Qs [NQ*CDIM];
__device__ float g_KVs[NQ*2*CDIM];
__device__ float g_hid[NQ*4*CDIM];
__device__ float g_po [NSPLIT*64*QPER*DH];  // partial O: [split][bh][qi][d]
__device__ float g_pm [NSPLIT*64*QPER];
__device__ float g_pl [NSPLIT*64*QPER];

// ---------------- RMSNorm: one block per row (C=256 threads) ---------------
__global__ void rmsnorm_k(const float* __restrict__ x, const float* __restrict__ w,
                          float* __restrict__ y)
{
    int row = blockIdx.x;
    int t = threadIdx.x;
    float v = x[(size_t)row*CDIM + t];
    float ss = v*v;
    // warp reduce
    #pragma unroll
    for (int o = 16; o > 0; o >>= 1) ss += __shfl_xor_sync(0xffffffffu, ss, o);
    __shared__ float red[8];
    if ((t & 31) == 0) red[t >> 5] = ss;
    __syncthreads();
    float tot;
    if (t < 8) {
        float r = red[t];
        #pragma unroll
        for (int o = 4; o > 0; o >>= 1) r += __shfl_xor_sync(0xffu, r, o);
        if (t == 0) red[0] = r;
    }
    __syncthreads();
    tot = red[0];
    float inv = rsqrtf(tot * (1.0f/CDIM) + RMS_EPS);
    y[(size_t)row*CDIM + t] = v * inv * w[t];
}

// ---------------- generic SGEMM: C = epi(A @ B^T) --------------------------
// A: [M,K] row-major, B: [N,K] row-major (weight layout [out,in]).
// mode 0: v*scale (+bias)(+res); mode 1: gelu_exact(v+bias); mode 2: log(sigmoid(v)+1e-6)
#define BM 64
#define BN 64
#define BKK 16
__global__ void gemm_tn(const float* __restrict__ A, const float* __restrict__ B,
                        const float* __restrict__ bias, const float* __restrict__ res,
                        float* __restrict__ C, int M, int N, int K,
                        long sA, long sB, long sC, float scale, int mode)
{
    A += (long)blockIdx.z * sA;
    B += (long)blockIdx.z * sB;
    C += (long)blockIdx.z * sC;
    __shared__ float As[BKK][BM];
    __shared__ float Bs[BKK][BN];
    int tid = threadIdx.x;
    int m0 = blockIdx.y * BM;
    int n0 = blockIdx.x * BN;
    int tx = tid & 15, ty = tid >> 4;
    int lr = tid >> 2;          // 0..63
    int lc = (tid & 3) << 2;    // 0,4,8,12
    float acc[4][4] = {};
    for (int kk = 0; kk < K; kk += BKK) {
        float4 av = *reinterpret_cast<const float4*>(&A[(size_t)(m0 + lr)*K + kk + lc]);
        float4 bv = *reinterpret_cast<const float4*>(&B[(size_t)(n0 + lr)*K + kk + lc]);
        As[lc+0][lr] = av.x; As[lc+1][lr] = av.y; As[lc+2][lr] = av.z; As[lc+3][lr] = av.w;
        Bs[lc+0][lr] = bv.x; Bs[lc+1][lr] = bv.y; Bs[lc+2][lr] = bv.z; Bs[lc+3][lr] = bv.w;
        __syncthreads();
        #pragma unroll
        for (int k = 0; k < BKK; ++k) {
            float4 a = *reinterpret_cast<const float4*>(&As[k][ty*4]);
            float4 b = *reinterpret_cast<const float4*>(&Bs[k][tx*4]);
            float ar[4] = {a.x, a.y, a.z, a.w};
            float br[4] = {b.x, b.y, b.z, b.w};
            #pragma unroll
            for (int i = 0; i < 4; ++i)
                #pragma unroll
                for (int j = 0; j < 4; ++j)
                    acc[i][j] = fmaf(ar[i], br[j], acc[i][j]);
        }
        __syncthreads();
    }
    #pragma unroll
    for (int i = 0; i < 4; ++i) {
        int mrow = m0 + ty*4 + i;
        #pragma unroll
        for (int j = 0; j < 4; ++j) {
            int ncol = n0 + tx*4 + j;
            float v = acc[i][j] * scale;
            if (mode == 1) {
                v += bias[ncol];
                v = 0.5f * v * (1.0f + erff(v * 0.70710678118654752f));
            } else if (mode == 2) {
                float sg = 1.0f / (1.0f + expf(-v));
                v = logf(sg + 1e-6f);
            } else {
                if (bias) v += bias[ncol];
                if (res)  v += res[(size_t)mrow*N + ncol];
            }
            C[(size_t)mrow*N + ncol] = v;
        }
    }
}

// ---------------- cross-attention (split-KV flash, block-diagonal) --------
// grid (64 = b*8+h, NSPLIT), block 128 (thread = query within batch)
__global__ void cross_attn_partial()
{
    int bh = blockIdx.x;
    int split = blockIdx.y;
    int b = bh >> 3, h = bh & 7;
    int i = threadIdx.x;
    int qi = b*QPER + i;
    const int KS = KVPER / NSPLIT;   // 256
    int j0 = split * KS;

    __shared__ float Ks[32][32];
    __shared__ float Vs[32][32];

    float qreg[DH];
    #pragma unroll
    for (int d = 0; d < DH; ++d) qreg[d] = g_Qc[(size_t)qi*CDIM + h*DH + d];

    float m = -1e30f, l = 0.0f;
    float oacc[DH] = {};
    const float* Kb = g_Kc + (size_t)(b*KVPER + j0)*CDIM + h*DH;
    const float* Vb = g_Vc + (size_t)(b*KVPER + j0)*CDIM + h*DH;
    const float* mb = g_zT + (size_t)b*KVPER*QPER + (size_t)j0*QPER + i;

    for (int jt = 0; jt < KS; jt += 32) {
        __syncthreads();
        for (int idx = i; idx < 1024; idx += 128) {
            int r = idx >> 5, cd = idx & 31;
            Ks[r][cd] = Kb[(size_t)(jt + r)*CDIM + cd];
            Vs[r][cd] = Vb[(size_t)(jt + r)*CDIM + cd];
        }
        __syncthreads();
        for (int j = 0; j < 32; ++j) {
            float s = mb[(size_t)(jt + j)*QPER];
            float s0 = 0.f, s1 = 0.f, s2 = 0.f, s3 = 0.f;
            #pragma unroll
            for (int d = 0; d < DH; d += 4) {
                s0 = fmaf(qreg[d+0], Ks[j][d+0], s0);
                s1 = fmaf(qreg[d+1], Ks[j][d+1], s1);
                s2 = fmaf(qreg[d+2], Ks[j][d+2], s2);
                s3 = fmaf(qreg[d+3], Ks[j][d+3], s3);
            }
            s += (s0 + s1) + (s2 + s3);
            if (s <= m) {
                float p = __expf(s - m);
                l += p;
                #pragma unroll
                for (int d = 0; d < DH; ++d) oacc[d] = fmaf(p, Vs[j][d], oacc[d]);
            } else {
                float corr = __expf(m - s);
                m = s;
                l = fmaf(l, corr, 1.0f);
                #pragma unroll
                for (int d = 0; d < DH; ++d) oacc[d] = fmaf(oacc[d], corr, Vs[j][d]);
            }
        }
    }
    int base = (split*64 + bh)*QPER + i;
    g_pm[base] = m;
    g_pl[base] = l;
    #pragma unroll
    for (int d = 0; d < DH; ++d) g_po[(size_t)base*DH + d] = oacc[d];
}

// combine: grid NQ, block 256 (thread = channel)
__global__ void cross_attn_combine()
{
    int qi = blockIdx.x;
    int c = threadIdx.x;
    int h = c >> 5, d = c & 31;
    int b = qi >> 7, i = qi & 127;
    int bh = b*8 + h;
    float mv[NSPLIT], lv[NSPLIT];
    float M = -1e30f;
    #pragma unroll
    for (int s = 0; s < NSPLIT; ++s) {
        int base = (s*64 + bh)*QPER + i;
        mv[s] = g_pm[base];
        lv[s] = g_pl[base];
        M = fmaxf(M, mv[s]);
    }
    float O = 0.f, L = 0.f;
    #pragma unroll
    for (int s = 0; s < NSPLIT; ++s) {
        float w = __expf(mv[s] - M);
        int base = (s*64 + bh)*QPER + i;
        O = fmaf(w, g_po[(size_t)base*DH + d], O);
        L = fmaf(w, lv[s], L);
    }
    g_attn[(size_t)qi*CDIM + c] = O / L;
}

// ---------------- self-attention (block-diagonal 128x128) -----------------
// grid 64 (b*8+h), block 128 (thread = query)
__global__ void self_attn()
{
    int bh = blockIdx.x;
    int b = bh >> 3, h = bh & 7;
    int i = threadIdx.x;
    int qi = b*QPER + i;

    __shared__ float Ks[32][32];
    __shared__ float Vs[32][32];

    float qreg[DH];
    #pragma unroll
    for (int d = 0; d < DH; ++d) qreg[d] = g_Qs[(size_t)qi*CDIM + h*DH + d];

    float m = -1e30f, l = 0.0f;
    float oacc[DH] = {};
    const float* KVb = g_KVs + (size_t)(b*QPER)*(2*CDIM) + h*DH;

    for (int jt = 0; jt < QPER; jt += 32) {
        __syncthreads();
        for (int idx = i; idx < 1024; idx += 128) {
            int r = idx >> 5, cd = idx & 31;
            Ks[r][cd] = KVb[(size_t)(jt + r)*(2*CDIM) + cd];
            Vs[r][cd] = KVb[(size_t)(jt + r)*(2*CDIM) + CDIM + cd];
        }
        __syncthreads();
        for (int j = 0; j < 32; ++j) {
            float s0 = 0.f, s1 = 0.f, s2 = 0.f, s3 = 0.f;
            #pragma unroll
            for (int d = 0; d < DH; d += 4) {
                s0 = fmaf(qreg[d+0], Ks[j][d+0], s0);
                s1 = fmaf(qreg[d+1], Ks[j][d+1], s1);
                s2 = fmaf(qreg[d+2], Ks[j][d+2], s2);
                s3 = fmaf(qreg[d+3], Ks[j][d+3], s3);
            }
            float s = (s0 + s1) + (s2 + s3);
            if (s <= m) {
                float p = __expf(s - m);
                l += p;
                #pragma unroll
                for (int d = 0; d < DH; ++d) oacc[d] = fmaf(p, Vs[j][d], oacc[d]);
            } else {
                float corr = __expf(m - s);
                m = s;
                l = fmaf(l, corr, 1.0f);
                #pragma unroll
                for (int d = 0; d < DH; ++d) oacc[d] = fmaf(oacc[d], corr, Vs[j][d]);
            }
        }
    }
    float inv = 1.0f / l;
    #pragma unroll
    for (int d = 0; d < DH; ++d)
        g_attn[(size_t)qi*CDIM + h*DH + d] = oacc[d] * inv;
}

// ---------------- launch ----------------------------------------------------
static inline float* sym(const void* symbol)
{
    void* p = nullptr;
    cudaGetSymbolAddress(&p, symbol);
    return (float*)p;
}

extern "C" void kernel_launch(void* const* d_in, const int* in_sizes, int n_in,
                              void* d_out, int out_size)
{
    const float* q        = (const float*)d_in[0];
    const float* kv       = (const float*)d_in[1];
    // d_in[2], d_in[3]: cu_seqlens (uniform segmentation, hardcoded)
    const float* w_norm_kv= (const float*)d_in[4];
    const float* w_norm1  = (const float*)d_in[5];
    const float* w_norm2  = (const float*)d_in[6];
    const float* w_norm3  = (const float*)d_in[7];
    const float* wq_c     = (const float*)d_in[8];
    const float* wk_c     = (const float*)d_in[9];
    const float* wv_c     = (const float*)d_in[10];
    const float* wo_c     = (const float*)d_in[11];
    const float* bo_c     = (const float*)d_in[12];
    const float* wq_s     = (const float*)d_in[13];
    const float* wkv_s    = (const float*)d_in[14];
    const float* wo_s     = (const float*)d_in[15];
    const float* bo_s     = (const float*)d_in[16];
    const float* w1_mlp   = (const float*)d_in[17];
    const float* b1_mlp   = (const float*)d_in[18];
    const float* w2_mlp   = (const float*)d_in[19];
    const float* b2_mlp   = (const float*)d_in[20];
    const float* w1_mask  = (const float*)d_in[21];
    const float* b1_mask  = (const float*)d_in[22];
    const float* w2_mask  = (const float*)d_in[23];
    const float* b2_mask  = (const float*)d_in[24];
    float* out = (float*)d_out;

    float* p_kvn = sym(g_kvn);
    float* p_Kc  = sym(g_Kc);
    float* p_Vc  = sym(g_Vc);
    float* p_mh  = sym(g_mh);
    float* p_mk  = sym(g_mk);
    float* p_zT  = sym(g_zT);
    float* p_qn  = sym(g_qn);
    float* p_Qc  = sym(g_Qc);
    float* p_attn= sym(g_attn);
    float* p_q1  = sym(g_q1);
    float* p_q2  = sym(g_q2);
    float* p_Qs  = sym(g_Qs);
    float* p_KVs = sym(g_KVs);
    float* p_hid = sym(g_hid);

    // 1. kv_n = rms(kv, w_norm_kv)
    rmsnorm_k<<<NKV, CDIM>>>(kv, w_norm_kv, p_kvn);
    // 2-3. mask MLP: mh = gelu(q @ w1_mask^T + b1), mk = mh @ w2_mask^T + b2
    gemm_tn<<<dim3(4,16,1), 256>>>(q,    w1_mask, b1_mask, nullptr, p_mh, NQ, CDIM, CDIM, 0,0,0, 1.f, 1);
    gemm_tn<<<dim3(4,16,1), 256>>>(p_mh, w2_mask, b2_mask, nullptr, p_mk, NQ, CDIM, CDIM, 0,0,0, 1.f, 0);
    // 4. zT[b] = log(sigmoid(kv_n[b] @ mk[b]^T)+1e-6)   [1024 kv x 128 q] per batch
    gemm_tn<<<dim3(2,16,BATCH), 256>>>(p_kvn, p_mk, nullptr, nullptr, p_zT,
                                       KVPER, QPER, CDIM,
                                       (long)KVPER*CDIM, (long)QPER*CDIM, (long)KVPER*QPER, 1.f, 2);
    // 5-6. K, V projections of kv_n
    gemm_tn<<<dim3(4,128,1), 256>>>(p_kvn, wk_c, nullptr, nullptr, p_Kc, NKV, CDIM, CDIM, 0,0,0, 1.f, 0);
    gemm_tn<<<dim3(4,128,1), 256>>>(p_kvn, wv_c, nullptr, nullptr, p_Vc, NKV, CDIM, CDIM, 0,0,0, 1.f, 0);
    // 7-8. q_n1, Q projection (scale folded in)
    rmsnorm_k<<<NQ, CDIM>>>(q, w_norm1, p_qn);
    gemm_tn<<<dim3(4,16,1), 256>>>(p_qn, wq_c, nullptr, nullptr, p_Qc, NQ, CDIM, CDIM, 0,0,0, ATTN_SCALE, 0);
    // 9-10. cross attention (block-diag + mask), split-KV
    cross_attn_partial<<<dim3(64, NSPLIT), 128>>>();
    cross_attn_combine<<<NQ, CDIM>>>();
    // 11. q1 = q + attn @ wo_c^T + bo_c
    gemm_tn<<<dim3(4,16,1), 256>>>(p_attn, wo_c, bo_c, q, p_q1, NQ, CDIM, CDIM, 0,0,0, 1.f, 0);
    // 12-14. self-attn projections
    rmsnorm_k<<<NQ, CDIM>>>(p_q1, w_norm2, p_qn);
    gemm_tn<<<dim3(4,16,1), 256>>>(p_qn, wq_s,  nullptr, nullptr, p_Qs,  NQ, CDIM,   CDIM, 0,0,0, ATTN_SCALE, 0);
    gemm_tn<<<dim3(8,16,1), 256>>>(p_qn, wkv_s, nullptr, nullptr, p_KVs, NQ, 2*CDIM, CDIM, 0,0,0, 1.f, 0);
    // 15. self attention (block-diag, no extra mask)
    self_attn<<<64, 128>>>();
    // 16. q2 = q1 + attn @ wo_s^T + bo_s
    gemm_tn<<<dim3(4,16,1), 256>>>(p_attn, wo_s, bo_s, p_q1, p_q2, NQ, CDIM, CDIM, 0,0,0, 1.f, 0);
    // 17-19. MLP with residual -> out
    rmsnorm_k<<<NQ, CDIM>>>(p_q2, w_norm3, p_qn);
    gemm_tn<<<dim3(16,16,1), 256>>>(p_qn,  w1_mlp, b1_mlp, nullptr, p_hid, NQ, 4*CDIM, CDIM,   0,0,0, 1.f, 1);
    gemm_tn<<<dim3(4,16,1),  256>>>(p_hid, w2_mlp, b2_mlp, p_q2,    out,   NQ, CDIM,   4*CDIM, 0,0,0, 1.f, 0);
}

// round 3
// speedup vs baseline: 1.3272x; 1.3272x over previous
#include <cuda_runtime.h>
#include <cuda_bf16.h>
#include <cstdint>
#include <math.h>

// ---------------- problem constants ----------------
#define CDIM 256
#define HEADS 8
#define DH 32
#define BATCH 8
#define QPER 128
#define KVPER 1024
#define NQ (BATCH*QPER)      // 1024
#define NKV (BATCH*KVPER)    // 8192
#define RMS_EPS 1.1920928955078125e-07f
#define ATTN_SCALE 0.17677669529663687f  // 1/sqrt(32)
#define NSPLIT 4             // cross-attn key splits

// ---------------- scratch (device globals; no cudaMalloc allowed) ----------
__device__ float g_kvn[NKV*CDIM];
__device__ float g_Kc [NKV*CDIM];
__device__ float g_Vc [NKV*CDIM];
__device__ float g_mh [NQ*CDIM];
__device__ float g_mk [NQ*CDIM];
__device__ float g_zT [BATCH*KVPER*QPER];   // per batch: [kv=1024][q=128]
__device__ float g_qn [NQ*CDIM];
__device__ float g_Qc [NQ*CDIM];
__device__ float g_attn[NQ*CDIM];
__device__ float g_q1 [NQ*CDIM];
__device__ float g_q2 [NQ*CDIM];
__device__ float g_Qs [NQ*CDIM];
__device__ float g_KVs[NQ*2*CDIM];
__device__ float g_hid[NQ*4*CDIM];
__device__ float g_po [NSPLIT*64*QPER*DH];
__device__ float g_pm [NSPLIT*64*QPER];
__device__ float g_pl [NSPLIT*64*QPER];

// ---------------- fast exp (poly, avoids MUFU) -----------------------------
__device__ __forceinline__ float fexp(float x) {
    float y = x * 1.44269504088896340736f;
    y = fminf(fmaxf(y, -126.0f), 126.0f);
    float r = rintf(y);
    float f = y - r;
    float p = 1.3333558146428443e-3f;
    p = fmaf(p, f, 9.6181291076284772e-3f);
    p = fmaf(p, f, 5.5504108664821580e-2f);
    p = fmaf(p, f, 2.4022650695910072e-1f);
    p = fmaf(p, f, 6.9314718055994531e-1f);
    p = fmaf(p, f, 1.0f);
    float s = __int_as_float(((int)r + 127) << 23);
    return p * s;
}

// ---------------- RMSNorm: one block per row (C=256 threads) ---------------
__global__ void rmsnorm_k(const float* __restrict__ x, const float* __restrict__ w,
                          float* __restrict__ y)
{
    int row = blockIdx.x;
    int t = threadIdx.x;
    float v = x[(size_t)row*CDIM + t];
    float ss = v*v;
    #pragma unroll
    for (int o = 16; o > 0; o >>= 1) ss += __shfl_xor_sync(0xffffffffu, ss, o);
    __shared__ float red[8];
    if ((t & 31) == 0) red[t >> 5] = ss;
    __syncthreads();
    float tot;
    if (t < 8) {
        float r = red[t];
        #pragma unroll
        for (int o = 4; o > 0; o >>= 1) r += __shfl_xor_sync(0xffu, r, o);
        if (t == 0) red[0] = r;
    }
    __syncthreads();
    tot = red[0];
    float inv = rsqrtf(tot * (1.0f/CDIM) + RMS_EPS);
    y[(size_t)row*CDIM + t] = v * inv * w[t];
}

// ---------------- tf32 tensor-core GEMM: C = epi(A @ B^T) ------------------
// A: [M,K] row-major, B: [N,K] row-major. BM=BN=64, BK=16, 128 threads (4 warps 2x2).
// mode 0: v*scale (+bias)(+res); mode 1: gelu_exact(v+bias); mode 2: log(sigmoid(v)+1e-6)
#define SPAD 20

__device__ __forceinline__ unsigned int to_tf32(float x) {
    unsigned int u;
    asm("cvt.rna.tf32.f32 %0, %1;" : "=r"(u) : "f"(x));
    return u;
}

#define MMA_TF32(acc, a, b) \
    asm volatile("mma.sync.aligned.m16n8k8.row.col.f32.tf32.tf32.f32 " \
        "{%0,%1,%2,%3}, {%4,%5,%6,%7}, {%8,%9}, {%0,%1,%2,%3};" \
        : "+f"(acc[0]), "+f"(acc[1]), "+f"(acc[2]), "+f"(acc[3]) \
        : "r"(a[0]), "r"(a[1]), "r"(a[2]), "r"(a[3]), "r"(b[0]), "r"(b[1]))

__global__ __launch_bounds__(128)
void gemm_mma(const float* __restrict__ A, const float* __restrict__ B,
              const float* __restrict__ bias, const float* __restrict__ res,
              float* __restrict__ C, int M, int N, int K,
              long sA, long sB, long sC, float scale, int mode)
{
    A += (long)blockIdx.z * sA;
    B += (long)blockIdx.z * sB;
    C += (long)blockIdx.z * sC;
    __shared__ unsigned int As[64][SPAD];
    __shared__ unsigned int Bs[64][SPAD];
    int tid = threadIdx.x;
    int warp = tid >> 5, lane = tid & 31;
    int wm = (warp >> 1) * 32, wn = (warp & 1) * 32;
    int g = lane >> 2, t = lane & 3;
    int m0 = blockIdx.y * 64, n0 = blockIdx.x * 64;

    int r0 = tid >> 2,         c0 = (tid & 3) * 4;           // idx 0..127
    int r1 = (tid + 128) >> 2, c1 = ((tid + 128) & 3) * 4;   // idx 128..255

    float c[2][4][4] = {};
    float4 pa0, pa1, pb0, pb1;

    // prefetch tile 0
    pa0 = *reinterpret_cast<const float4*>(&A[(size_t)(m0 + r0)*K + c0]);
    pa1 = *reinterpret_cast<const float4*>(&A[(size_t)(m0 + r1)*K + c1]);
    pb0 = *reinterpret_cast<const float4*>(&B[(size_t)(n0 + r0)*K + c0]);
    pb1 = *reinterpret_cast<const float4*>(&B[(size_t)(n0 + r1)*K + c1]);

    for (int kk = 0; kk < K; kk += 16) {
        // commit prefetched tile to smem (tf32 bits)
        As[r0][c0+0] = to_tf32(pa0.x); As[r0][c0+1] = to_tf32(pa0.y);
        As[r0][c0+2] = to_tf32(pa0.z); As[r0][c0+3] = to_tf32(pa0.w);
        As[r1][c1+0] = to_tf32(pa1.x); As[r1][c1+1] = to_tf32(pa1.y);
        As[r1][c1+2] = to_tf32(pa1.z); As[r1][c1+3] = to_tf32(pa1.w);
        Bs[r0][c0+0] = to_tf32(pb0.x); Bs[r0][c0+1] = to_tf32(pb0.y);
        Bs[r0][c0+2] = to_tf32(pb0.z); Bs[r0][c0+3] = to_tf32(pb0.w);
        Bs[r1][c1+0] = to_tf32(pb1.x); Bs[r1][c1+1] = to_tf32(pb1.y);
        Bs[r1][c1+2] = to_tf32(pb1.z); Bs[r1][c1+3] = to_tf32(pb1.w);
        __syncthreads();

        if (kk + 16 < K) {
            int kn = kk + 16;
            pa0 = *reinterpret_cast<const float4*>(&A[(size_t)(m0 + r0)*K + kn + c0]);
            pa1 = *reinterpret_cast<const float4*>(&A[(size_t)(m0 + r1)*K + kn + c1]);
            pb0 = *reinterpret_cast<const float4*>(&B[(size_t)(n0 + r0)*K + kn + c0]);
            pb1 = *reinterpret_cast<const float4*>(&B[(size_t)(n0 + r1)*K + kn + c1]);
        }

        #pragma unroll
        for (int ks = 0; ks < 2; ++ks) {
            int kb = ks * 8;
            unsigned int af[2][4], bf[4][2];
            #pragma unroll
            for (int mt = 0; mt < 2; ++mt) {
                int rr = wm + mt*16;
                af[mt][0] = As[rr + g    ][kb + t];
                af[mt][1] = As[rr + g + 8][kb + t];
                af[mt][2] = As[rr + g    ][kb + t + 4];
                af[mt][3] = As[rr + g + 8][kb + t + 4];
            }
            #pragma unroll
            for (int nt = 0; nt < 4; ++nt) {
                int cn = wn + nt*8;
                bf[nt][0] = Bs[cn + g][kb + t];
                bf[nt][1] = Bs[cn + g][kb + t + 4];
            }
            #pragma unroll
            for (int mt = 0; mt < 2; ++mt)
                #pragma unroll
                for (int nt = 0; nt < 4; ++nt)
                    MMA_TF32(c[mt][nt], af[mt], bf[nt]);
        }
        __syncthreads();
    }

    // epilogue
    #pragma unroll
    for (int mt = 0; mt < 2; ++mt) {
        #pragma unroll
        for (int nt = 0; nt < 4; ++nt) {
            float* cc = c[mt][nt];
            int row = m0 + wm + mt*16 + g;
            int col = n0 + wn + nt*8 + 2*t;
            #pragma unroll
            for (int hh = 0; hh < 2; ++hh) {
                int rr = row + hh*8;
                float v0 = cc[hh*2+0] * scale;
                float v1 = cc[hh*2+1] * scale;
                if (mode == 1) {
                    v0 += bias[col];   v1 += bias[col+1];
                    v0 = 0.5f * v0 * (1.0f + erff(v0 * 0.70710678118654752f));
                    v1 = 0.5f * v1 * (1.0f + erff(v1 * 0.70710678118654752f));
                } else if (mode == 2) {
                    float u0 = 1.0f + fexp(-v0);
                    float u1 = 1.0f + fexp(-v1);
                    v0 = __logf(fmaf(1e-6f, u0, 1.0f)) - __logf(u0);
                    v1 = __logf(fmaf(1e-6f, u1, 1.0f)) - __logf(u1);
                } else {
                    if (bias) { v0 += bias[col]; v1 += bias[col+1]; }
                    if (res)  { v0 += res[(size_t)rr*N + col]; v1 += res[(size_t)rr*N + col + 1]; }
                }
                *reinterpret_cast<float2*>(&C[(size_t)rr*N + col]) = make_float2(v0, v1);
            }
        }
    }
}

// ---------------- cross-attention (split-KV flash, block-diagonal) --------
__global__ void cross_attn_partial()
{
    int bh = blockIdx.x;
    int split = blockIdx.y;
    int b = bh >> 3, h = bh & 7;
    int i = threadIdx.x;
    int qi = b*QPER + i;
    const int KS = KVPER / NSPLIT;   // 256
    int j0 = split * KS;

    __shared__ float Ks[32][32];
    __shared__ float Vs[32][32];

    float qreg[DH];
    #pragma unroll
    for (int d = 0; d < DH; ++d) qreg[d] = g_Qc[(size_t)qi*CDIM + h*DH + d];

    float m = -1e30f, l = 0.0f;
    float oacc[DH] = {};
    const float* Kb = g_Kc + (size_t)(b*KVPER + j0)*CDIM + h*DH;
    const float* Vb = g_Vc + (size_t)(b*KVPER + j0)*CDIM + h*DH;
    const float* mb = g_zT + (size_t)b*KVPER*QPER + (size_t)j0*QPER + i;

    for (int jt = 0; jt < KS; jt += 32) {
        __syncthreads();
        for (int idx = i; idx < 1024; idx += 128) {
            int r = idx >> 5, cd = idx & 31;
            Ks[r][cd] = Kb[(size_t)(jt + r)*CDIM + cd];
            Vs[r][cd] = Vb[(size_t)(jt + r)*CDIM + cd];
        }
        __syncthreads();
        for (int j = 0; j < 32; ++j) {
            float s = mb[(size_t)(jt + j)*QPER];
            float s0 = 0.f, s1 = 0.f, s2 = 0.f, s3 = 0.f;
            #pragma unroll
            for (int d = 0; d < DH; d += 4) {
                s0 = fmaf(qreg[d+0], Ks[j][d+0], s0);
                s1 = fmaf(qreg[d+1], Ks[j][d+1], s1);
                s2 = fmaf(qreg[d+2], Ks[j][d+2], s2);
                s3 = fmaf(qreg[d+3], Ks[j][d+3], s3);
            }
            s += (s0 + s1) + (s2 + s3);
            if (s <= m) {
                float p = __expf(s - m);
                l += p;
                #pragma unroll
                for (int d = 0; d < DH; ++d) oacc[d] = fmaf(p, Vs[j][d], oacc[d]);
            } else {
                float corr = __expf(m - s);
                m = s;
                l = fmaf(l, corr, 1.0f);
                #pragma unroll
                for (int d = 0; d < DH; ++d) oacc[d] = fmaf(oacc[d], corr, Vs[j][d]);
            }
        }
    }
    int base = (split*64 + bh)*QPER + i;
    g_pm[base] = m;
    g_pl[base] = l;
    #pragma unroll
    for (int d = 0; d < DH; ++d) g_po[(size_t)base*DH + d] = oacc[d];
}

__global__ void cross_attn_combine()
{
    int qi = blockIdx.x;
    int c = threadIdx.x;
    int h = c >> 5, d = c & 31;
    int b = qi >> 7, i = qi & 127;
    int bh = b*8 + h;
    float mv[NSPLIT], lv[NSPLIT];
    float M = -1e30f;
    #pragma unroll
    for (int s = 0; s < NSPLIT; ++s) {
        int base = (s*64 + bh)*QPER + i;
        mv[s] = g_pm[base];
        lv[s] = g_pl[base];
        M = fmaxf(M, mv[s]);
    }
    float O = 0.f, L = 0.f;
    #pragma unroll
    for (int s = 0; s < NSPLIT; ++s) {
        float w = __expf(mv[s] - M);
        int base = (s*64 + bh)*QPER + i;
        O = fmaf(w, g_po[(size_t)base*DH + d], O);
        L = fmaf(w, lv[s], L);
    }
    g_attn[(size_t)qi*CDIM + c] = O / L;
}

// ---------------- self-attention (block-diagonal 128x128) -----------------
__global__ void self_attn()
{
    int bh = blockIdx.x;
    int b = bh >> 3, h = bh & 7;
    int i = threadIdx.x;
    int qi = b*QPER + i;

    __shared__ float Ks[32][32];
    __shared__ float Vs[32][32];

    float qreg[DH];
    #pragma unroll
    for (int d = 0; d < DH; ++d) qreg[d] = g_Qs[(size_t)qi*CDIM + h*DH + d];

    float m = -1e30f, l = 0.0f;
    float oacc[DH] = {};
    const float* KVb = g_KVs + (size_t)(b*QPER)*(2*CDIM) + h*DH;

    for (int jt = 0; jt < QPER; jt += 32) {
        __syncthreads();
        for (int idx = i; idx < 1024; idx += 128) {
            int r = idx >> 5, cd = idx & 31;
            Ks[r][cd] = KVb[(size_t)(jt + r)*(2*CDIM) + cd];
            Vs[r][cd] = KVb[(size_t)(jt + r)*(2*CDIM) + CDIM + cd];
        }
        __syncthreads();
        for (int j = 0; j < 32; ++j) {
            float s0 = 0.f, s1 = 0.f, s2 = 0.f, s3 = 0.f;
            #pragma unroll
            for (int d = 0; d < DH; d += 4) {
                s0 = fmaf(qreg[d+0], Ks[j][d+0], s0);
                s1 = fmaf(qreg[d+1], Ks[j][d+1], s1);
                s2 = fmaf(qreg[d+2], Ks[j][d+2], s2);
                s3 = fmaf(qreg[d+3], Ks[j][d+3], s3);
            }
            float s = (s0 + s1) + (s2 + s3);
            if (s <= m) {
                float p = __expf(s - m);
                l += p;
                #pragma unroll
                for (int d = 0; d < DH; ++d) oacc[d] = fmaf(p, Vs[j][d], oacc[d]);
            } else {
                float corr = __expf(m - s);
                m = s;
                l = fmaf(l, corr, 1.0f);
                #pragma unroll
                for (int d = 0; d < DH; ++d) oacc[d] = fmaf(oacc[d], corr, Vs[j][d]);
            }
        }
    }
    float inv = 1.0f / l;
    #pragma unroll
    for (int d = 0; d < DH; ++d)
        g_attn[(size_t)qi*CDIM + h*DH + d] = oacc[d] * inv;
}

// ---------------- launch ----------------------------------------------------
static inline float* sym(const void* symbol)
{
    void* p = nullptr;
    cudaGetSymbolAddress(&p, symbol);
    return (float*)p;
}

extern "C" void kernel_launch(void* const* d_in, const int* in_sizes, int n_in,
                              void* d_out, int out_size)
{
    const float* q        = (const float*)d_in[0];
    const float* kv       = (const float*)d_in[1];
    const float* w_norm_kv= (const float*)d_in[4];
    const float* w_norm1  = (const float*)d_in[5];
    const float* w_norm2  = (const float*)d_in[6];
    const float* w_norm3  = (const float*)d_in[7];
    const float* wq_c     = (const float*)d_in[8];
    const float* wk_c     = (const float*)d_in[9];
    const float* wv_c     = (const float*)d_in[10];
    const float* wo_c     = (const float*)d_in[11];
    const float* bo_c     = (const float*)d_in[12];
    const float* wq_s     = (const float*)d_in[13];
    const float* wkv_s    = (const float*)d_in[14];
    const float* wo_s     = (const float*)d_in[15];
    const float* bo_s     = (const float*)d_in[16];
    const float* w1_mlp   = (const float*)d_in[17];
    const float* b1_mlp   = (const float*)d_in[18];
    const float* w2_mlp   = (const float*)d_in[19];
    const float* b2_mlp   = (const float*)d_in[20];
    const float* w1_mask  = (const float*)d_in[21];
    const float* b1_mask  = (const float*)d_in[22];
    const float* w2_mask  = (const float*)d_in[23];
    const float* b2_mask  = (const float*)d_in[24];
    float* out = (float*)d_out;

    float* p_kvn = sym(g_kvn);
    float* p_Kc  = sym(g_Kc);
    float* p_Vc  = sym(g_Vc);
    float* p_mh  = sym(g_mh);
    float* p_mk  = sym(g_mk);
    float* p_zT  = sym(g_zT);
    float* p_qn  = sym(g_qn);
    float* p_Qc  = sym(g_Qc);
    float* p_attn= sym(g_attn);
    float* p_q1  = sym(g_q1);
    float* p_q2  = sym(g_q2);
    float* p_Qs  = sym(g_Qs);
    float* p_KVs = sym(g_KVs);
    float* p_hid = sym(g_hid);

    // 1. kv_n = rms(kv, w_norm_kv)
    rmsnorm_k<<<NKV, CDIM>>>(kv, w_norm_kv, p_kvn);
    // 2-3. mask MLP
    gemm_mma<<<dim3(4,16,1), 128>>>(q,    w1_mask, b1_mask, nullptr, p_mh, NQ, CDIM, CDIM, 0,0,0, 1.f, 1);
    gemm_mma<<<dim3(4,16,1), 128>>>(p_mh, w2_mask, b2_mask, nullptr, p_mk, NQ, CDIM, CDIM, 0,0,0, 1.f, 0);
    // 4. zT[b] = log(sigmoid(kv_n[b] @ mk[b]^T)+1e-6)
    gemm_mma<<<dim3(2,16,BATCH), 128>>>(p_kvn, p_mk, nullptr, nullptr, p_zT,
                                        KVPER, QPER, CDIM,
                                        (long)KVPER*CDIM, (long)QPER*CDIM, (long)KVPER*QPER, 1.f, 2);
    // 5-6. K, V projections of kv_n
    gemm_mma<<<dim3(4,128,1), 128>>>(p_kvn, wk_c, nullptr, nullptr, p_Kc, NKV, CDIM, CDIM, 0,0,0, 1.f, 0);
    gemm_mma<<<dim3(4,128,1), 128>>>(p_kvn, wv_c, nullptr, nullptr, p_Vc, NKV, CDIM, CDIM, 0,0,0, 1.f, 0);
    // 7-8. q_n1, Q projection (scale folded in)
    rmsnorm_k<<<NQ, CDIM>>>(q, w_norm1, p_qn);
    gemm_mma<<<dim3(4,16,1), 128>>>(p_qn, wq_c, nullptr, nullptr, p_Qc, NQ, CDIM, CDIM, 0,0,0, ATTN_SCALE, 0);
    // 9-10. cross attention
    cross_attn_partial<<<dim3(64, NSPLIT), 128>>>();
    cross_attn_combine<<<NQ, CDIM>>>();
    // 11. q1 = q + attn @ wo_c^T + bo_c
    gemm_mma<<<dim3(4,16,1), 128>>>(p_attn, wo_c, bo_c, q, p_q1, NQ, CDIM, CDIM, 0,0,0, 1.f, 0);
    // 12-14. self-attn projections
    rmsnorm_k<<<NQ, CDIM>>>(p_q1, w_norm2, p_qn);
    gemm_mma<<<dim3(4,16,1), 128>>>(p_qn, wq_s,  nullptr, nullptr, p_Qs,  NQ, CDIM,   CDIM, 0,0,0, ATTN_SCALE, 0);
    gemm_mma<<<dim3(8,16,1), 128>>>(p_qn, wkv_s, nullptr, nullptr, p_KVs, NQ, 2*CDIM, CDIM, 0,0,0, 1.f, 0);
    // 15. self attention
    self_attn<<<64, 128>>>();
    // 16. q2 = q1 + attn @ wo_s^T + bo_s
    gemm_mma<<<dim3(4,16,1), 128>>>(p_attn, wo_s, bo_s, p_q1, p_q2, NQ, CDIM, CDIM, 0,0,0, 1.f, 0);
    // 17-19. MLP with residual -> out
    rmsnorm_k<<<NQ, CDIM>>>(p_q2, w_norm3, p_qn);
    gemm_mma<<<dim3(16,16,1), 128>>>(p_qn,  w1_mlp, b1_mlp, nullptr, p_hid, NQ, 4*CDIM, CDIM,   0,0,0, 1.f, 1);
    gemm_mma<<<dim3(4,16,1),  128>>>(p_hid, w2_mlp, b2_mlp, p_q2,    out,   NQ, CDIM,   4*CDIM, 0,0,0, 1.f, 0);
}

// round 4
// speedup vs baseline: 1.7034x; 1.2835x over previous
#include <cuda_runtime.h>
#include <cuda_bf16.h>
#include <cstdint>
#include <math.h>

// ---------------- problem constants ----------------
#define CDIM 256
#define HEADS 8
#define DH 32
#define BATCH 8
#define QPER 128
#define KVPER 1024
#define NQ (BATCH*QPER)      // 1024
#define NKV (BATCH*KVPER)    // 8192
#define RMS_EPS 1.1920928955078125e-07f
#define ATTN_SCALE 0.17677669529663687f  // 1/sqrt(32)
#define NSPLIT 4             // cross-attn key splits

// ---------------- scratch (device globals; no cudaMalloc allowed) ----------
__device__ __align__(16) float g_kvn[NKV*CDIM];
__device__ __align__(16) float g_Kc [NKV*CDIM];
__device__ __align__(16) float g_Vc [NKV*CDIM];
__device__ __align__(16) float g_mh [NQ*CDIM];
__device__ __align__(16) float g_mk [NQ*CDIM];
__device__ __align__(16) float g_zT [BATCH*KVPER*QPER];   // per batch: [kv][q]
__device__ __align__(16) float g_qn [NQ*CDIM];
__device__ __align__(16) float g_Qc [NQ*CDIM];
__device__ __align__(16) float g_attn[NQ*CDIM];
__device__ __align__(16) float g_q1 [NQ*CDIM];
__device__ __align__(16) float g_q2 [NQ*CDIM];
__device__ __align__(16) float g_Qs [NQ*CDIM];
__device__ __align__(16) float g_KVs[NQ*2*CDIM];
__device__ __align__(16) float g_hid[NQ*4*CDIM];
__device__ __align__(16) float g_po [NSPLIT*64*QPER*DH];
__device__ __align__(16) float g_pm [NSPLIT*64*QPER];
__device__ __align__(16) float g_pl [NSPLIT*64*QPER];

// ---------------- fast exp / log (FMA-pipe polys, no MUFU) -----------------
__device__ __forceinline__ float fexp(float x) {
    float y = x * 1.44269504088896340736f;
    y = fminf(fmaxf(y, -126.0f), 126.0f);
    float r = rintf(y);
    float f = y - r;
    float p = 1.3333558146428443e-3f;
    p = fmaf(p, f, 9.6181291076284772e-3f);
    p = fmaf(p, f, 5.5504108664821580e-2f);
    p = fmaf(p, f, 2.4022650695910072e-1f);
    p = fmaf(p, f, 6.9314718055994531e-1f);
    p = fmaf(p, f, 1.0f);
    float s = __int_as_float(((int)r + 127) << 23);
    return p * s;
}

__device__ __forceinline__ float flog(float x) {
    int ix = __float_as_int(x);
    int e = (ix - 0x3f3504f3) >> 23;           // mantissa in [sqrt(.5), sqrt(2))
    float m = __int_as_float(ix - (e << 23));
    float f = m - 1.0f;
    float z = f * f;
    float p = 7.0376836292e-2f;
    p = fmaf(p, f, -1.1514610310e-1f);
    p = fmaf(p, f,  1.1676998740e-1f);
    p = fmaf(p, f, -1.2420140846e-1f);
    p = fmaf(p, f,  1.4249322787e-1f);
    p = fmaf(p, f, -1.6668057665e-1f);
    p = fmaf(p, f,  2.0000714765e-1f);
    p = fmaf(p, f, -2.4999993993e-1f);
    p = fmaf(p, f,  3.3333331174e-1f);
    float y = f * z * p;
    y = fmaf(-0.5f, z, y);
    return fmaf((float)e, 0.693147180559945f, f + y);
}

// ---------------- RMSNorm: one block per row (C=256 threads) ---------------
__global__ void rmsnorm_k(const float* __restrict__ x, const float* __restrict__ w,
                          float* __restrict__ y)
{
    int row = blockIdx.x;
    int t = threadIdx.x;
    float v = x[(size_t)row*CDIM + t];
    float ss = v*v;
    #pragma unroll
    for (int o = 16; o > 0; o >>= 1) ss += __shfl_xor_sync(0xffffffffu, ss, o);
    __shared__ float red[8];
    if ((t & 31) == 0) red[t >> 5] = ss;
    __syncthreads();
    float tot;
    if (t < 8) {
        float r = red[t];
        #pragma unroll
        for (int o = 4; o > 0; o >>= 1) r += __shfl_xor_sync(0xffu, r, o);
        if (t == 0) red[0] = r;
    }
    __syncthreads();
    tot = red[0];
    float inv = rsqrtf(tot * (1.0f/CDIM) + RMS_EPS);
    y[(size_t)row*CDIM + t] = v * inv * w[t];
}

// ---------------- pipelined tf32 tensor-core GEMM: C = epi(A @ B^T) --------
// A: [M,K] row-major, B: [N,K] row-major. BN=64, BK=16, 3-stage cp.async,
// 128 threads. BM templated (64 for big-M, 32 for M=1024 launches).
// mode 0: v*scale (+bias)(+res); mode 1: gelu_exact(v+bias); mode 2: log(sigmoid+1e-6)

__device__ __forceinline__ void cp_async16(void* smem, const void* gmem) {
    unsigned s = (unsigned)__cvta_generic_to_shared(smem);
    asm volatile("cp.async.cg.shared.global [%0], [%1], 16;\n" :: "r"(s), "l"(gmem));
}
#define CP_COMMIT() asm volatile("cp.async.commit_group;\n" ::: "memory")
#define CP_WAIT1()  asm volatile("cp.async.wait_group 1;\n" ::: "memory")

#define MMA_TF32(acc, a, b) \
    asm volatile("mma.sync.aligned.m16n8k8.row.col.f32.tf32.tf32.f32 " \
        "{%0,%1,%2,%3}, {%4,%5,%6,%7}, {%8,%9}, {%0,%1,%2,%3};" \
        : "+f"(acc[0]), "+f"(acc[1]), "+f"(acc[2]), "+f"(acc[3]) \
        : "r"(a[0]), "r"(a[1]), "r"(a[2]), "r"(a[3]), "r"(b[0]), "r"(b[1]))

template<int BM>
__device__ __forceinline__ void stage_load(float (*As)[20], float (*Bs)[20],
    const float* __restrict__ A, const float* __restrict__ B,
    int m0, int n0, int K, int kk, int tid)
{
    constexpr int CHA = BM*4;
    constexpr int TOT = (BM+64)*4;
    #pragma unroll
    for (int i = 0; i < TOT/128; ++i) {
        int ch = tid + i*128;
        if (ch < CHA) {
            int r = ch >> 2, c = (ch & 3) << 2;
            cp_async16(&As[r][c], &A[(size_t)(m0 + r)*K + kk + c]);
        } else {
            int ch2 = ch - CHA;
            int r = ch2 >> 2, c = (ch2 & 3) << 2;
            cp_async16(&Bs[r][c], &B[(size_t)(n0 + r)*K + kk + c]);
        }
    }
}

template<int BM>
__global__ __launch_bounds__(128)
void gemm_cp(const float* __restrict__ A, const float* __restrict__ B,
             const float* __restrict__ bias, const float* __restrict__ res,
             float* __restrict__ C, int N, int K,
             long sA, long sB, long sC, float scale, int mode)
{
    A += (long)blockIdx.z * sA;
    B += (long)blockIdx.z * sB;
    C += (long)blockIdx.z * sC;
    __shared__ float As[3][BM][20];
    __shared__ float Bs[3][64][20];

    constexpr int WARPS_N = (BM == 64) ? 2 : 4;
    constexpr int WN_EXT  = 64 / WARPS_N;      // 32 or 16
    constexpr int NT      = WN_EXT / 8;        // 4 or 2

    int tid = threadIdx.x;
    int warp = tid >> 5, lane = tid & 31;
    int wm = (warp / WARPS_N) * 32;
    int wn = (warp % WARPS_N) * WN_EXT;
    int g = lane >> 2, t = lane & 3;
    int m0 = blockIdx.y * BM, n0 = blockIdx.x * 64;

    float acc[2][NT][4];
    #pragma unroll
    for (int i = 0; i < 2; ++i)
        #pragma unroll
        for (int j = 0; j < NT; ++j)
            #pragma unroll
            for (int k = 0; k < 4; ++k) acc[i][j][k] = 0.f;

    int NIT = K >> 4;
    stage_load<BM>(As[0], Bs[0], A, B, m0, n0, K, 0, tid);  CP_COMMIT();
    stage_load<BM>(As[1], Bs[1], A, B, m0, n0, K, 16, tid); CP_COMMIT();

    for (int it = 0; it < NIT; ++it) {
        CP_WAIT1();
        __syncthreads();
        int st = it % 3;
        #pragma unroll
        for (int ks = 0; ks < 2; ++ks) {
            int kb = ks * 8;
            unsigned af[2][4], bf[NT][2];
            #pragma unroll
            for (int mt = 0; mt < 2; ++mt) {
                int rr = wm + mt*16;
                af[mt][0] = __float_as_uint(As[st][rr + g    ][kb + t]);
                af[mt][1] = __float_as_uint(As[st][rr + g + 8][kb + t]);
                af[mt][2] = __float_as_uint(As[st][rr + g    ][kb + t + 4]);
                af[mt][3] = __float_as_uint(As[st][rr + g + 8][kb + t + 4]);
            }
            #pragma unroll
            for (int nt = 0; nt < NT; ++nt) {
                int cn = wn + nt*8;
                bf[nt][0] = __float_as_uint(Bs[st][cn + g][kb + t]);
                bf[nt][1] = __float_as_uint(Bs[st][cn + g][kb + t + 4]);
            }
            #pragma unroll
            for (int mt = 0; mt < 2; ++mt)
                #pragma unroll
                for (int nt = 0; nt < NT; ++nt)
                    MMA_TF32(acc[mt][nt], af[mt], bf[nt]);
        }
        int nx = it + 2;
        if (nx < NIT)
            stage_load<BM>(As[nx % 3], Bs[nx % 3], A, B, m0, n0, K, nx*16, tid);
        CP_COMMIT();
    }

    // epilogue
    #pragma unroll
    for (int mt = 0; mt < 2; ++mt) {
        #pragma unroll
        for (int nt = 0; nt < NT; ++nt) {
            float* cc = acc[mt][nt];
            int row = m0 + wm + mt*16 + g;
            int col = n0 + wn + nt*8 + 2*t;
            #pragma unroll
            for (int hh = 0; hh < 2; ++hh) {
                int rr = row + hh*8;
                float v0 = cc[hh*2+0] * scale;
                float v1 = cc[hh*2+1] * scale;
                if (mode == 1) {
                    v0 += bias[col];   v1 += bias[col+1];
                    v0 = 0.5f * v0 * (1.0f + erff(v0 * 0.70710678118654752f));
                    v1 = 0.5f * v1 * (1.0f + erff(v1 * 0.70710678118654752f));
                } else if (mode == 2) {
                    float u0 = 1.0f + fexp(-v0);
                    float u1 = 1.0f + fexp(-v1);
                    v0 = flog(fmaf(1e-6f, u0, 1.0f)) - flog(u0);
                    v1 = flog(fmaf(1e-6f, u1, 1.0f)) - flog(u1);
                } else {
                    if (bias) { v0 += bias[col]; v1 += bias[col+1]; }
                    if (res)  { v0 += res[(size_t)rr*N + col]; v1 += res[(size_t)rr*N + col + 1]; }
                }
                *reinterpret_cast<float2*>(&C[(size_t)rr*N + col]) = make_float2(v0, v1);
            }
        }
    }
}

// ---------------- cross-attention (split-KV flash, block-diagonal) --------
__global__ void cross_attn_partial()
{
    int bh = blockIdx.x;
    int split = blockIdx.y;
    int b = bh >> 3, h = bh & 7;
    int i = threadIdx.x;
    int qi = b*QPER + i;
    const int KS = KVPER / NSPLIT;   // 256
    int j0 = split * KS;

    __shared__ float Ks[32][32];
    __shared__ float Vs[32][32];

    float qreg[DH];
    #pragma unroll
    for (int d = 0; d < DH; ++d) qreg[d] = g_Qc[(size_t)qi*CDIM + h*DH + d];

    float m = -1e30f, l = 0.0f;
    float oacc[DH] = {};
    const float* Kb = g_Kc + (size_t)(b*KVPER + j0)*CDIM + h*DH;
    const float* Vb = g_Vc + (size_t)(b*KVPER + j0)*CDIM + h*DH;
    const float* mb = g_zT + (size_t)b*KVPER*QPER + (size_t)j0*QPER + i;

    for (int jt = 0; jt < KS; jt += 32) {
        __syncthreads();
        for (int idx = i; idx < 1024; idx += 128) {
            int r = idx >> 5, cd = idx & 31;
            Ks[r][cd] = Kb[(size_t)(jt + r)*CDIM + cd];
            Vs[r][cd] = Vb[(size_t)(jt + r)*CDIM + cd];
        }
        __syncthreads();
        for (int j = 0; j < 32; ++j) {
            float s = mb[(size_t)(jt + j)*QPER];
            float s0 = 0.f, s1 = 0.f, s2 = 0.f, s3 = 0.f;
            #pragma unroll
            for (int d = 0; d < DH; d += 4) {
                s0 = fmaf(qreg[d+0], Ks[j][d+0], s0);
                s1 = fmaf(qreg[d+1], Ks[j][d+1], s1);
                s2 = fmaf(qreg[d+2], Ks[j][d+2], s2);
                s3 = fmaf(qreg[d+3], Ks[j][d+3], s3);
            }
            s += (s0 + s1) + (s2 + s3);
            if (s <= m) {
                float p = fexp(s - m);
                l += p;
                #pragma unroll
                for (int d = 0; d < DH; ++d) oacc[d] = fmaf(p, Vs[j][d], oacc[d]);
            } else {
                float corr = fexp(m - s);
                m = s;
                l = fmaf(l, corr, 1.0f);
                #pragma unroll
                for (int d = 0; d < DH; ++d) oacc[d] = fmaf(oacc[d], corr, Vs[j][d]);
            }
        }
    }
    int base = (split*64 + bh)*QPER + i;
    g_pm[base] = m;
    g_pl[base] = l;
    #pragma unroll
    for (int d = 0; d < DH; ++d) g_po[(size_t)base*DH + d] = oacc[d];
}

__global__ void cross_attn_combine()
{
    int qi = blockIdx.x;
    int c = threadIdx.x;
    int h = c >> 5, d = c & 31;
    int b = qi >> 7, i = qi & 127;
    int bh = b*8 + h;
    float mv[NSPLIT], lv[NSPLIT];
    float M = -1e30f;
    #pragma unroll
    for (int s = 0; s < NSPLIT; ++s) {
        int base = (s*64 + bh)*QPER + i;
        mv[s] = g_pm[base];
        lv[s] = g_pl[base];
        M = fmaxf(M, mv[s]);
    }
    float O = 0.f, L = 0.f;
    #pragma unroll
    for (int s = 0; s < NSPLIT; ++s) {
        float w = fexp(mv[s] - M);
        int base = (s*64 + bh)*QPER + i;
        O = fmaf(w, g_po[(size_t)base*DH + d], O);
        L = fmaf(w, lv[s], L);
    }
    g_attn[(size_t)qi*CDIM + c] = O / L;
}

// ---------------- self-attention (block-diagonal 128x128) -----------------
__global__ void self_attn()
{
    int bh = blockIdx.x;
    int b = bh >> 3, h = bh & 7;
    int i = threadIdx.x;
    int qi = b*QPER + i;

    __shared__ float Ks[32][32];
    __shared__ float Vs[32][32];

    float qreg[DH];
    #pragma unroll
    for (int d = 0; d < DH; ++d) qreg[d] = g_Qs[(size_t)qi*CDIM + h*DH + d];

    float m = -1e30f, l = 0.0f;
    float oacc[DH] = {};
    const float* KVb = g_KVs + (size_t)(b*QPER)*(2*CDIM) + h*DH;

    for (int jt = 0; jt < QPER; jt += 32) {
        __syncthreads();
        for (int idx = i; idx < 1024; idx += 128) {
            int r = idx >> 5, cd = idx & 31;
            Ks[r][cd] = KVb[(size_t)(jt + r)*(2*CDIM) + cd];
            Vs[r][cd] = KVb[(size_t)(jt + r)*(2*CDIM) + CDIM + cd];
        }
        __syncthreads();
        for (int j = 0; j < 32; ++j) {
            float s0 = 0.f, s1 = 0.f, s2 = 0.f, s3 = 0.f;
            #pragma unroll
            for (int d = 0; d < DH; d += 4) {
                s0 = fmaf(qreg[d+0], Ks[j][d+0], s0);
                s1 = fmaf(qreg[d+1], Ks[j][d+1], s1);
                s2 = fmaf(qreg[d+2], Ks[j][d+2], s2);
                s3 = fmaf(qreg[d+3], Ks[j][d+3], s3);
            }
            float s = (s0 + s1) + (s2 + s3);
            if (s <= m) {
                float p = fexp(s - m);
                l += p;
                #pragma unroll
                for (int d = 0; d < DH; ++d) oacc[d] = fmaf(p, Vs[j][d], oacc[d]);
            } else {
                float corr = fexp(m - s);
                m = s;
                l = fmaf(l, corr, 1.0f);
                #pragma unroll
                for (int d = 0; d < DH; ++d) oacc[d] = fmaf(oacc[d], corr, Vs[j][d]);
            }
        }
    }
    float inv = 1.0f / l;
    #pragma unroll
    for (int d = 0; d < DH; ++d)
        g_attn[(size_t)qi*CDIM + h*DH + d] = oacc[d] * inv;
}

// ---------------- launch ----------------------------------------------------
static inline float* sym(const void* symbol)
{
    void* p = nullptr;
    cudaGetSymbolAddress(&p, symbol);
    return (float*)p;
}

extern "C" void kernel_launch(void* const* d_in, const int* in_sizes, int n_in,
                              void* d_out, int out_size)
{
    const float* q        = (const float*)d_in[0];
    const float* kv       = (const float*)d_in[1];
    const float* w_norm_kv= (const float*)d_in[4];
    const float* w_norm1  = (const float*)d_in[5];
    const float* w_norm2  = (const float*)d_in[6];
    const float* w_norm3  = (const float*)d_in[7];
    const float* wq_c     = (const float*)d_in[8];
    const float* wk_c     = (const float*)d_in[9];
    const float* wv_c     = (const float*)d_in[10];
    const float* wo_c     = (const float*)d_in[11];
    const float* bo_c     = (const float*)d_in[12];
    const float* wq_s     = (const float*)d_in[13];
    const float* wkv_s    = (const float*)d_in[14];
    const float* wo_s     = (const float*)d_in[15];
    const float* bo_s     = (const float*)d_in[16];
    const float* w1_mlp   = (const float*)d_in[17];
    const float* b1_mlp   = (const float*)d_in[18];
    const float* w2_mlp   = (const float*)d_in[19];
    const float* b2_mlp   = (const float*)d_in[20];
    const float* w1_mask  = (const float*)d_in[21];
    const float* b1_mask  = (const float*)d_in[22];
    const float* w2_mask  = (const float*)d_in[23];
    const float* b2_mask  = (const float*)d_in[24];
    float* out = (float*)d_out;

    float* p_kvn = sym(g_kvn);
    float* p_Kc  = sym(g_Kc);
    float* p_Vc  = sym(g_Vc);
    float* p_mh  = sym(g_mh);
    float* p_mk  = sym(g_mk);
    float* p_zT  = sym(g_zT);
    float* p_qn  = sym(g_qn);
    float* p_Qc  = sym(g_Qc);
    float* p_attn= sym(g_attn);
    float* p_q1  = sym(g_q1);
    float* p_q2  = sym(g_q2);
    float* p_Qs  = sym(g_Qs);
    float* p_KVs = sym(g_KVs);
    float* p_hid = sym(g_hid);

    // 1. kv_n = rms(kv, w_norm_kv)
    rmsnorm_k<<<NKV, CDIM>>>(kv, w_norm_kv, p_kvn);
    // 2-3. mask MLP
    gemm_cp<32><<<dim3(4,32,1), 128>>>(q,    w1_mask, b1_mask, nullptr, p_mh, CDIM, CDIM, 0,0,0, 1.f, 1);
    gemm_cp<32><<<dim3(4,32,1), 128>>>(p_mh, w2_mask, b2_mask, nullptr, p_mk, CDIM, CDIM, 0,0,0, 1.f, 0);
    // 4. zT[b] = log(sigmoid(kv_n[b] @ mk[b]^T)+1e-6)
    gemm_cp<64><<<dim3(2,16,BATCH), 128>>>(p_kvn, p_mk, nullptr, nullptr, p_zT,
                                           QPER, CDIM,
                                           (long)KVPER*CDIM, (long)QPER*CDIM, (long)KVPER*QPER, 1.f, 2);
    // 5-6. K, V projections of kv_n
    gemm_cp<64><<<dim3(4,128,1), 128>>>(p_kvn, wk_c, nullptr, nullptr, p_Kc, CDIM, CDIM, 0,0,0, 1.f, 0);
    gemm_cp<64><<<dim3(4,128,1), 128>>>(p_kvn, wv_c, nullptr, nullptr, p_Vc, CDIM, CDIM, 0,0,0, 1.f, 0);
    // 7-8. q_n1, Q projection (scale folded in)
    rmsnorm_k<<<NQ, CDIM>>>(q, w_norm1, p_qn);
    gemm_cp<32><<<dim3(4,32,1), 128>>>(p_qn, wq_c, nullptr, nullptr, p_Qc, CDIM, CDIM, 0,0,0, ATTN_SCALE, 0);
    // 9-10. cross attention
    cross_attn_partial<<<dim3(64, NSPLIT), 128>>>();
    cross_attn_combine<<<NQ, CDIM>>>();
    // 11. q1 = q + attn @ wo_c^T + bo_c
    gemm_cp<32><<<dim3(4,32,1), 128>>>(p_attn, wo_c, bo_c, q, p_q1, CDIM, CDIM, 0,0,0, 1.f, 0);
    // 12-14. self-attn projections
    rmsnorm_k<<<NQ, CDIM>>>(p_q1, w_norm2, p_qn);
    gemm_cp<32><<<dim3(4,32,1), 128>>>(p_qn, wq_s,  nullptr, nullptr, p_Qs,  CDIM,   CDIM, 0,0,0, ATTN_SCALE, 0);
    gemm_cp<32><<<dim3(8,32,1), 128>>>(p_qn, wkv_s, nullptr, nullptr, p_KVs, 2*CDIM, CDIM, 0,0,0, 1.f, 0);
    // 15. self attention
    self_attn<<<64, 128>>>();
    // 16. q2 = q1 + attn @ wo_s^T + bo_s
    gemm_cp<32><<<dim3(4,32,1), 128>>>(p_attn, wo_s, bo_s, p_q1, p_q2, CDIM, CDIM, 0,0,0, 1.f, 0);
    // 17-19. MLP with residual -> out
    rmsnorm_k<<<NQ, CDIM>>>(p_q2, w_norm3, p_qn);
    gemm_cp<64><<<dim3(16,16,1), 128>>>(p_qn,  w1_mlp, b1_mlp, nullptr, p_hid, 4*CDIM, CDIM,   0,0,0, 1.f, 1);
    gemm_cp<32><<<dim3(4,32,1),  128>>>(p_hid, w2_mlp, b2_mlp, p_q2,    out,   CDIM,   4*CDIM, 0,0,0, 1.f, 0);
}

// round 5
// speedup vs baseline: 2.1333x; 1.2524x over previous
#include <cuda_runtime.h>
#include <cuda_bf16.h>
#include <cstdint>
#include <math.h>

// ---------------- problem constants ----------------
#define CDIM 256
#define HEADS 8
#define DH 32
#define BATCH 8
#define QPER 128
#define KVPER 1024
#define NQ (BATCH*QPER)      // 1024
#define NKV (BATCH*KVPER)    // 8192
#define RMS_EPS 1.1920928955078125e-07f
#define ATTN_SCALE 0.17677669529663687f  // 1/sqrt(32)
#define NSPLIT 8             // cross-attn key splits

// ---------------- scratch (device globals; no cudaMalloc allowed) ----------
__device__ __align__(16) float g_kvn[NKV*CDIM];
__device__ __align__(16) float g_Kc [NKV*CDIM];
__device__ __align__(16) float g_Vc [NKV*CDIM];
__device__ __align__(16) float g_mh [NQ*CDIM];
__device__ __align__(16) float g_mk [NQ*CDIM];
__device__ __align__(16) float g_zT [BATCH*KVPER*QPER];   // per batch: [kv][q]
__device__ __align__(16) float g_qn [NQ*CDIM];
__device__ __align__(16) float g_Qc [NQ*CDIM];
__device__ __align__(16) float g_attn[NQ*CDIM];
__device__ __align__(16) float g_q1 [NQ*CDIM];
__device__ __align__(16) float g_q2 [NQ*CDIM];
__device__ __align__(16) float g_Qs [NQ*CDIM];
__device__ __align__(16) float g_KVs[NQ*2*CDIM];
__device__ __align__(16) float g_hid[NQ*4*CDIM];
__device__ __align__(16) float g_po [NSPLIT*64*QPER*DH];
__device__ __align__(16) float g_pm [NSPLIT*64*QPER];
__device__ __align__(16) float g_pl [NSPLIT*64*QPER];

// ---------------- fast exp / log (FMA-pipe polys, no MUFU) -----------------
__device__ __forceinline__ float fexp(float x) {
    float y = x * 1.44269504088896340736f;
    y = fminf(fmaxf(y, -126.0f), 126.0f);
    float r = rintf(y);
    float f = y - r;
    float p = 1.3333558146428443e-3f;
    p = fmaf(p, f, 9.6181291076284772e-3f);
    p = fmaf(p, f, 5.5504108664821580e-2f);
    p = fmaf(p, f, 2.4022650695910072e-1f);
    p = fmaf(p, f, 6.9314718055994531e-1f);
    p = fmaf(p, f, 1.0f);
    float s = __int_as_float(((int)r + 127) << 23);
    return p * s;
}

__device__ __forceinline__ float flog(float x) {
    int ix = __float_as_int(x);
    int e = (ix - 0x3f3504f3) >> 23;           // mantissa in [sqrt(.5), sqrt(2))
    float m = __int_as_float(ix - (e << 23));
    float f = m - 1.0f;
    float z = f * f;
    float p = 7.0376836292e-2f;
    p = fmaf(p, f, -1.1514610310e-1f);
    p = fmaf(p, f,  1.1676998740e-1f);
    p = fmaf(p, f, -1.2420140846e-1f);
    p = fmaf(p, f,  1.4249322787e-1f);
    p = fmaf(p, f, -1.6668057665e-1f);
    p = fmaf(p, f,  2.0000714765e-1f);
    p = fmaf(p, f, -2.4999993993e-1f);
    p = fmaf(p, f,  3.3333331174e-1f);
    float y = f * z * p;
    y = fmaf(-0.5f, z, y);
    return fmaf((float)e, 0.693147180559945f, f + y);
}

// ---------------- RMSNorm: one block per row (C=256 threads) ---------------
__global__ void rmsnorm_k(const float* __restrict__ x, const float* __restrict__ w,
                          float* __restrict__ y)
{
    int row = blockIdx.x;
    int t = threadIdx.x;
    float v = x[(size_t)row*CDIM + t];
    float ss = v*v;
    #pragma unroll
    for (int o = 16; o > 0; o >>= 1) ss += __shfl_xor_sync(0xffffffffu, ss, o);
    __shared__ float red[8];
    if ((t & 31) == 0) red[t >> 5] = ss;
    __syncthreads();
    float tot;
    if (t < 8) {
        float r = red[t];
        #pragma unroll
        for (int o = 4; o > 0; o >>= 1) r += __shfl_xor_sync(0xffu, r, o);
        if (t == 0) red[0] = r;
    }
    __syncthreads();
    tot = red[0];
    float inv = rsqrtf(tot * (1.0f/CDIM) + RMS_EPS);
    y[(size_t)row*CDIM + t] = v * inv * w[t];
}

// ---------------- pipelined tf32 tensor-core GEMM: C = epi(A @ B^T) --------
// A: [M,K] row-major, B: [N,K] row-major. BN=64, BK=32, 2-stage cp.async.
// BM/THREADS templated. warps: (BM/32) x (THREADS/32/(BM/32)); warp tile 32x16.
// mode 0: v*scale (+bias)(+res); mode 1: gelu_exact(v+bias); mode 2: log(sigmoid+1e-6)

#define PADK 36

__device__ __forceinline__ void cp_async16(void* smem, const void* gmem) {
    unsigned s = (unsigned)__cvta_generic_to_shared(smem);
    asm volatile("cp.async.cg.shared.global [%0], [%1], 16;\n" :: "r"(s), "l"(gmem));
}
#define CP_COMMIT() asm volatile("cp.async.commit_group;\n" ::: "memory")
#define CP_WAIT1()  asm volatile("cp.async.wait_group 1;\n" ::: "memory")
#define CP_WAIT0()  asm volatile("cp.async.wait_group 0;\n" ::: "memory")

#define MMA_TF32(acc, a, b) \
    asm volatile("mma.sync.aligned.m16n8k8.row.col.f32.tf32.tf32.f32 " \
        "{%0,%1,%2,%3}, {%4,%5,%6,%7}, {%8,%9}, {%0,%1,%2,%3};" \
        : "+f"(acc[0]), "+f"(acc[1]), "+f"(acc[2]), "+f"(acc[3]) \
        : "r"(a[0]), "r"(a[1]), "r"(a[2]), "r"(a[3]), "r"(b[0]), "r"(b[1]))

template<int BM, int THREADS>
__device__ __forceinline__ void stage_load(float (*As)[PADK], float (*Bs)[PADK],
    const float* __restrict__ A, const float* __restrict__ B,
    int m0, int n0, int K, int kk, int tid)
{
    constexpr int CHA = BM*8;          // float4 chunks for A (BK=32 -> 8/row)
    constexpr int TOT = (BM+64)*8;
    #pragma unroll
    for (int i = 0; i < TOT/THREADS; ++i) {
        int ch = tid + i*THREADS;
        if (ch < CHA) {
            int r = ch >> 3, c = (ch & 7) << 2;
            cp_async16(&As[r][c], &A[(size_t)(m0 + r)*K + kk + c]);
        } else {
            int ch2 = ch - CHA;
            int r = ch2 >> 3, c = (ch2 & 7) << 2;
            cp_async16(&Bs[r][c], &B[(size_t)(n0 + r)*K + kk + c]);
        }
    }
}

template<int BM, int THREADS>
__global__ __launch_bounds__(THREADS)
void gemm_cp(const float* __restrict__ A, const float* __restrict__ B,
             const float* __restrict__ bias, const float* __restrict__ res,
             float* __restrict__ C, int N, int K,
             long sA, long sB, long sC, float scale, int mode)
{
    A += (long)blockIdx.z * sA;
    B += (long)blockIdx.z * sB;
    C += (long)blockIdx.z * sC;
    __shared__ __align__(16) float As[2][BM][PADK];
    __shared__ __align__(16) float Bs[2][64][PADK];

    constexpr int WARPS_M = BM / 32;
    constexpr int WARPS_N = (THREADS/32) / WARPS_M;   // 4
    int tid = threadIdx.x;
    int warp = tid >> 5, lane = tid & 31;
    int wm = (warp / WARPS_N) * 32;
    int wn = (warp % WARPS_N) * 16;
    int g = lane >> 2, t = lane & 3;
    int m0 = blockIdx.y * BM, n0 = blockIdx.x * 64;

    float acc[2][2][4];
    #pragma unroll
    for (int i = 0; i < 2; ++i)
        #pragma unroll
        for (int j = 0; j < 2; ++j)
            #pragma unroll
            for (int k = 0; k < 4; ++k) acc[i][j][k] = 0.f;

    int NIT = K >> 5;
    stage_load<BM,THREADS>(As[0], Bs[0], A, B, m0, n0, K, 0, tid);
    CP_COMMIT();

    for (int it = 0; it < NIT; ++it) {
        if (it + 1 < NIT) {
            stage_load<BM,THREADS>(As[(it+1)&1], Bs[(it+1)&1], A, B, m0, n0, K, (it+1)*32, tid);
            CP_COMMIT();
            CP_WAIT1();
        } else {
            CP_WAIT0();
        }
        __syncthreads();
        int st = it & 1;
        #pragma unroll
        for (int ks = 0; ks < 4; ++ks) {
            int kb = ks * 8;
            unsigned af[2][4], bf[2][2];
            #pragma unroll
            for (int mt = 0; mt < 2; ++mt) {
                int rr = wm + mt*16;
                af[mt][0] = __float_as_uint(As[st][rr + g    ][kb + t]);
                af[mt][1] = __float_as_uint(As[st][rr + g + 8][kb + t]);
                af[mt][2] = __float_as_uint(As[st][rr + g    ][kb + t + 4]);
                af[mt][3] = __float_as_uint(As[st][rr + g + 8][kb + t + 4]);
            }
            #pragma unroll
            for (int nt = 0; nt < 2; ++nt) {
                int cn = wn + nt*8;
                bf[nt][0] = __float_as_uint(Bs[st][cn + g][kb + t]);
                bf[nt][1] = __float_as_uint(Bs[st][cn + g][kb + t + 4]);
            }
            #pragma unroll
            for (int mt = 0; mt < 2; ++mt)
                #pragma unroll
                for (int nt = 0; nt < 2; ++nt)
                    MMA_TF32(acc[mt][nt], af[mt], bf[nt]);
        }
        __syncthreads();
    }

    // epilogue
    #pragma unroll
    for (int mt = 0; mt < 2; ++mt) {
        #pragma unroll
        for (int nt = 0; nt < 2; ++nt) {
            float* cc = acc[mt][nt];
            int row = m0 + wm + mt*16 + g;
            int col = n0 + wn + nt*8 + 2*t;
            #pragma unroll
            for (int hh = 0; hh < 2; ++hh) {
                int rr = row + hh*8;
                float v0 = cc[hh*2+0] * scale;
                float v1 = cc[hh*2+1] * scale;
                if (mode == 1) {
                    v0 += bias[col];   v1 += bias[col+1];
                    v0 = 0.5f * v0 * (1.0f + erff(v0 * 0.70710678118654752f));
                    v1 = 0.5f * v1 * (1.0f + erff(v1 * 0.70710678118654752f));
                } else if (mode == 2) {
                    float u0 = 1.0f + fexp(-v0);
                    float u1 = 1.0f + fexp(-v1);
                    v0 = flog(fmaf(1e-6f, u0, 1.0f)) - flog(u0);
                    v1 = flog(fmaf(1e-6f, u1, 1.0f)) - flog(u1);
                } else {
                    if (bias) { v0 += bias[col]; v1 += bias[col+1]; }
                    if (res)  { v0 += res[(size_t)rr*N + col]; v1 += res[(size_t)rr*N + col + 1]; }
                }
                *reinterpret_cast<float2*>(&C[(size_t)rr*N + col]) = make_float2(v0, v1);
            }
        }
    }
}

// ---------------- cross-attention (split-KV flash, block-diagonal) --------
__global__ void cross_attn_partial()
{
    int bh = blockIdx.x;
    int split = blockIdx.y;
    int b = bh >> 3, h = bh & 7;
    int i = threadIdx.x;
    int qi = b*QPER + i;
    const int KS = KVPER / NSPLIT;   // 128
    int j0 = split * KS;

    __shared__ float Ks[32][32];
    __shared__ float Vs[32][32];

    float qreg[DH];
    #pragma unroll
    for (int d = 0; d < DH; ++d) qreg[d] = g_Qc[(size_t)qi*CDIM + h*DH + d];

    float m = -1e30f, l = 0.0f;
    float oacc[DH] = {};
    const float* Kb = g_Kc + (size_t)(b*KVPER + j0)*CDIM + h*DH;
    const float* Vb = g_Vc + (size_t)(b*KVPER + j0)*CDIM + h*DH;
    const float* mb = g_zT + (size_t)b*KVPER*QPER + (size_t)j0*QPER + i;

    for (int jt = 0; jt < KS; jt += 32) {
        __syncthreads();
        for (int idx = i; idx < 1024; idx += 128) {
            int r = idx >> 5, cd = idx & 31;
            Ks[r][cd] = Kb[(size_t)(jt + r)*CDIM + cd];
            Vs[r][cd] = Vb[(size_t)(jt + r)*CDIM + cd];
        }
        __syncthreads();
        for (int j = 0; j < 32; ++j) {
            float s = mb[(size_t)(jt + j)*QPER];
            float s0 = 0.f, s1 = 0.f, s2 = 0.f, s3 = 0.f;
            #pragma unroll
            for (int d = 0; d < DH; d += 4) {
                s0 = fmaf(qreg[d+0], Ks[j][d+0], s0);
                s1 = fmaf(qreg[d+1], Ks[j][d+1], s1);
                s2 = fmaf(qreg[d+2], Ks[j][d+2], s2);
                s3 = fmaf(qreg[d+3], Ks[j][d+3], s3);
            }
            s += (s0 + s1) + (s2 + s3);
            if (s <= m) {
                float p = fexp(s - m);
                l += p;
                #pragma unroll
                for (int d = 0; d < DH; ++d) oacc[d] = fmaf(p, Vs[j][d], oacc[d]);
            } else {
                float corr = fexp(m - s);
                m = s;
                l = fmaf(l, corr, 1.0f);
                #pragma unroll
                for (int d = 0; d < DH; ++d) oacc[d] = fmaf(oacc[d], corr, Vs[j][d]);
            }
        }
    }
    int base = (split*64 + bh)*QPER + i;
    g_pm[base] = m;
    g_pl[base] = l;
    #pragma unroll
    for (int d = 0; d < DH; ++d) g_po[(size_t)base*DH + d] = oacc[d];
}

__global__ void cross_attn_combine()
{
    int qi = blockIdx.x;
    int c = threadIdx.x;
    int h = c >> 5, d = c & 31;
    int b = qi >> 7, i = qi & 127;
    int bh = b*8 + h;
    float mv[NSPLIT], lv[NSPLIT];
    float M = -1e30f;
    #pragma unroll
    for (int s = 0; s < NSPLIT; ++s) {
        int base = (s*64 + bh)*QPER + i;
        mv[s] = g_pm[base];
        lv[s] = g_pl[base];
        M = fmaxf(M, mv[s]);
    }
    float O = 0.f, L = 0.f;
    #pragma unroll
    for (int s = 0; s < NSPLIT; ++s) {
        float w = fexp(mv[s] - M);
        int base = (s*64 + bh)*QPER + i;
        O = fmaf(w, g_po[(size_t)base*DH + d], O);
        L = fmaf(w, lv[s], L);
    }
    g_attn[(size_t)qi*CDIM + c] = O / L;
}

// ---------------- self-attention (block-diagonal 128x128) -----------------
__global__ void self_attn()
{
    int bh = blockIdx.x;
    int b = bh >> 3, h = bh & 7;
    int i = threadIdx.x;
    int qi = b*QPER + i;

    __shared__ float Ks[32][32];
    __shared__ float Vs[32][32];

    float qreg[DH];
    #pragma unroll
    for (int d = 0; d < DH; ++d) qreg[d] = g_Qs[(size_t)qi*CDIM + h*DH + d];

    float m = -1e30f, l = 0.0f;
    float oacc[DH] = {};
    const float* KVb = g_KVs + (size_t)(b*QPER)*(2*CDIM) + h*DH;

    for (int jt = 0; jt < QPER; jt += 32) {
        __syncthreads();
        for (int idx = i; idx < 1024; idx += 128) {
            int r = idx >> 5, cd = idx & 31;
            Ks[r][cd] = KVb[(size_t)(jt + r)*(2*CDIM) + cd];
            Vs[r][cd] = KVb[(size_t)(jt + r)*(2*CDIM) + CDIM + cd];
        }
        __syncthreads();
        for (int j = 0; j < 32; ++j) {
            float s0 = 0.f, s1 = 0.f, s2 = 0.f, s3 = 0.f;
            #pragma unroll
            for (int d = 0; d < DH; d += 4) {
                s0 = fmaf(qreg[d+0], Ks[j][d+0], s0);
                s1 = fmaf(qreg[d+1], Ks[j][d+1], s1);
                s2 = fmaf(qreg[d+2], Ks[j][d+2], s2);
                s3 = fmaf(qreg[d+3], Ks[j][d+3], s3);
            }
            float s = (s0 + s1) + (s2 + s3);
            if (s <= m) {
                float p = fexp(s - m);
                l += p;
                #pragma unroll
                for (int d = 0; d < DH; ++d) oacc[d] = fmaf(p, Vs[j][d], oacc[d]);
            } else {
                float corr = fexp(m - s);
                m = s;
                l = fmaf(l, corr, 1.0f);
                #pragma unroll
                for (int d = 0; d < DH; ++d) oacc[d] = fmaf(oacc[d], corr, Vs[j][d]);
            }
        }
    }
    float inv = 1.0f / l;
    #pragma unroll
    for (int d = 0; d < DH; ++d)
        g_attn[(size_t)qi*CDIM + h*DH + d] = oacc[d] * inv;
}

// ---------------- launch ----------------------------------------------------
static inline float* sym(const void* symbol)
{
    void* p = nullptr;
    cudaGetSymbolAddress(&p, symbol);
    return (float*)p;
}

extern "C" void kernel_launch(void* const* d_in, const int* in_sizes, int n_in,
                              void* d_out, int out_size)
{
    const float* q        = (const float*)d_in[0];
    const float* kv       = (const float*)d_in[1];
    const float* w_norm_kv= (const float*)d_in[4];
    const float* w_norm1  = (const float*)d_in[5];
    const float* w_norm2  = (const float*)d_in[6];
    const float* w_norm3  = (const float*)d_in[7];
    const float* wq_c     = (const float*)d_in[8];
    const float* wk_c     = (const float*)d_in[9];
    const float* wv_c     = (const float*)d_in[10];
    const float* wo_c     = (const float*)d_in[11];
    const float* bo_c     = (const float*)d_in[12];
    const float* wq_s     = (const float*)d_in[13];
    const float* wkv_s    = (const float*)d_in[14];
    const float* wo_s     = (const float*)d_in[15];
    const float* bo_s     = (const float*)d_in[16];
    const float* w1_mlp   = (const float*)d_in[17];
    const float* b1_mlp   = (const float*)d_in[18];
    const float* w2_mlp   = (const float*)d_in[19];
    const float* b2_mlp   = (const float*)d_in[20];
    const float* w1_mask  = (const float*)d_in[21];
    const float* b1_mask  = (const float*)d_in[22];
    const float* w2_mask  = (const float*)d_in[23];
    const float* b2_mask  = (const float*)d_in[24];
    float* out = (float*)d_out;

    float* p_kvn = sym(g_kvn);
    float* p_Kc  = sym(g_Kc);
    float* p_Vc  = sym(g_Vc);
    float* p_mh  = sym(g_mh);
    float* p_mk  = sym(g_mk);
    float* p_zT  = sym(g_zT);
    float* p_qn  = sym(g_qn);
    float* p_Qc  = sym(g_Qc);
    float* p_attn= sym(g_attn);
    float* p_q1  = sym(g_q1);
    float* p_q2  = sym(g_q2);
    float* p_Qs  = sym(g_Qs);
    float* p_KVs = sym(g_KVs);
    float* p_hid = sym(g_hid);

    // 1. kv_n = rms(kv, w_norm_kv)
    rmsnorm_k<<<NKV, CDIM>>>(kv, w_norm_kv, p_kvn);
    // 2-3. mask MLP
    gemm_cp<32,128><<<dim3(4,32,1), 128>>>(q,    w1_mask, b1_mask, nullptr, p_mh, CDIM, CDIM, 0,0,0, 1.f, 1);
    gemm_cp<32,128><<<dim3(4,32,1), 128>>>(p_mh, w2_mask, b2_mask, nullptr, p_mk, CDIM, CDIM, 0,0,0, 1.f, 0);
    // 4. zT[b] = log(sigmoid(kv_n[b] @ mk[b]^T)+1e-6)
    gemm_cp<64,256><<<dim3(2,16,BATCH), 256>>>(p_kvn, p_mk, nullptr, nullptr, p_zT,
                                               QPER, CDIM,
                                               (long)KVPER*CDIM, (long)QPER*CDIM, (long)KVPER*QPER, 1.f, 2);
    // 5-6. K, V projections of kv_n
    gemm_cp<64,256><<<dim3(4,128,1), 256>>>(p_kvn, wk_c, nullptr, nullptr, p_Kc, CDIM, CDIM, 0,0,0, 1.f, 0);
    gemm_cp<64,256><<<dim3(4,128,1), 256>>>(p_kvn, wv_c, nullptr, nullptr, p_Vc, CDIM, CDIM, 0,0,0, 1.f, 0);
    // 7-8. q_n1, Q projection (scale folded in)
    rmsnorm_k<<<NQ, CDIM>>>(q, w_norm1, p_qn);
    gemm_cp<32,128><<<dim3(4,32,1), 128>>>(p_qn, wq_c, nullptr, nullptr, p_Qc, CDIM, CDIM, 0,0,0, ATTN_SCALE, 0);
    // 9-10. cross attention
    cross_attn_partial<<<dim3(64, NSPLIT), 128>>>();
    cross_attn_combine<<<NQ, CDIM>>>();
    // 11. q1 = q + attn @ wo_c^T + bo_c
    gemm_cp<32,128><<<dim3(4,32,1), 128>>>(p_attn, wo_c, bo_c, q, p_q1, CDIM, CDIM, 0,0,0, 1.f, 0);
    // 12-14. self-attn projections
    rmsnorm_k<<<NQ, CDIM>>>(p_q1, w_norm2, p_qn);
    gemm_cp<32,128><<<dim3(4,32,1), 128>>>(p_qn, wq_s,  nullptr, nullptr, p_Qs,  CDIM,   CDIM, 0,0,0, ATTN_SCALE, 0);
    gemm_cp<32,128><<<dim3(8,32,1), 128>>>(p_qn, wkv_s, nullptr, nullptr, p_KVs, 2*CDIM, CDIM, 0,0,0, 1.f, 0);
    // 15. self attention
    self_attn<<<64, 128>>>();
    // 16. q2 = q1 + attn @ wo_s^T + bo_s
    gemm_cp<32,128><<<dim3(4,32,1), 128>>>(p_attn, wo_s, bo_s, p_q1, p_q2, CDIM, CDIM, 0,0,0, 1.f, 0);
    // 17-19. MLP with residual -> out
    rmsnorm_k<<<NQ, CDIM>>>(p_q2, w_norm3, p_qn);
    gemm_cp<64,256><<<dim3(16,16,1), 256>>>(p_qn,  w1_mlp, b1_mlp, nullptr, p_hid, 4*CDIM, CDIM,   0,0,0, 1.f, 1);
    gemm_cp<32,128><<<dim3(4,32,1),  128>>>(p_hid, w2_mlp, b2_mlp, p_q2,    out,   CDIM,   4*CDIM, 0,0,0, 1.f, 0);
}

// round 6
// speedup vs baseline: 2.2296x; 1.0451x over previous
#include <cuda_runtime.h>
#include <cuda_bf16.h>
#include <cstdint>
#include <math.h>

// ---------------- problem constants ----------------
#define CDIM 256
#define HEADS 8
#define DH 32
#define BATCH 8
#define QPER 128
#define KVPER 1024
#define NQ (BATCH*QPER)      // 1024
#define NKV (BATCH*KVPER)    // 8192
#define RMS_EPS 1.1920928955078125e-07f
#define ATTN_SCALE 0.17677669529663687f  // 1/sqrt(32)
#define NSPLIT 8             // cross-attn key splits

// ---------------- scratch (device globals; no cudaMalloc allowed) ----------
__device__ __align__(16) float g_kvn[NKV*CDIM];
__device__ __align__(16) float g_Kc [NKV*CDIM];
__device__ __align__(16) float g_Vc [NKV*CDIM];
__device__ __align__(16) float g_mh [NQ*CDIM];
__device__ __align__(16) float g_mk [NQ*CDIM];
__device__ __align__(16) float g_zT [BATCH*KVPER*QPER];   // per batch: [kv][q]
__device__ __align__(16) float g_qn [NQ*CDIM];
__device__ __align__(16) float g_Qc [NQ*CDIM];
__device__ __align__(16) float g_attn[NQ*CDIM];
__device__ __align__(16) float g_q1 [NQ*CDIM];
__device__ __align__(16) float g_q2 [NQ*CDIM];
__device__ __align__(16) float g_Qs [NQ*CDIM];
__device__ __align__(16) float g_KVs[NQ*2*CDIM];
__device__ __align__(16) float g_hid[NQ*4*CDIM];
__device__ __align__(16) float g_po [NSPLIT*64*QPER*DH];
__device__ __align__(16) float g_pm [NSPLIT*64*QPER];
__device__ __align__(16) float g_pl [NSPLIT*64*QPER];

// ---------------- fast exp / log (FMA-pipe polys, no MUFU) -----------------
__device__ __forceinline__ float fexp(float x) {
    float y = x * 1.44269504088896340736f;
    y = fminf(fmaxf(y, -126.0f), 126.0f);
    float r = rintf(y);
    float f = y - r;
    float p = 1.3333558146428443e-3f;
    p = fmaf(p, f, 9.6181291076284772e-3f);
    p = fmaf(p, f, 5.5504108664821580e-2f);
    p = fmaf(p, f, 2.4022650695910072e-1f);
    p = fmaf(p, f, 6.9314718055994531e-1f);
    p = fmaf(p, f, 1.0f);
    float s = __int_as_float(((int)r + 127) << 23);
    return p * s;
}

__device__ __forceinline__ float flog(float x) {
    int ix = __float_as_int(x);
    int e = (ix - 0x3f3504f3) >> 23;
    float m = __int_as_float(ix - (e << 23));
    float f = m - 1.0f;
    float z = f * f;
    float p = 7.0376836292e-2f;
    p = fmaf(p, f, -1.1514610310e-1f);
    p = fmaf(p, f,  1.1676998740e-1f);
    p = fmaf(p, f, -1.2420140846e-1f);
    p = fmaf(p, f,  1.4249322787e-1f);
    p = fmaf(p, f, -1.6668057665e-1f);
    p = fmaf(p, f,  2.0000714765e-1f);
    p = fmaf(p, f, -2.4999993993e-1f);
    p = fmaf(p, f,  3.3333331174e-1f);
    float y = f * z * p;
    y = fmaf(-0.5f, z, y);
    return fmaf((float)e, 0.693147180559945f, f + y);
}

// ---------------- RMSNorm ----------------------------------------------------
__global__ void rmsnorm_k(const float* __restrict__ x, const float* __restrict__ w,
                          float* __restrict__ y)
{
    int row = blockIdx.x;
    int t = threadIdx.x;
    float v = x[(size_t)row*CDIM + t];
    float ss = v*v;
    #pragma unroll
    for (int o = 16; o > 0; o >>= 1) ss += __shfl_xor_sync(0xffffffffu, ss, o);
    __shared__ float red[8];
    if ((t & 31) == 0) red[t >> 5] = ss;
    __syncthreads();
    float tot;
    if (t < 8) {
        float r = red[t];
        #pragma unroll
        for (int o = 4; o > 0; o >>= 1) r += __shfl_xor_sync(0xffu, r, o);
        if (t == 0) red[0] = r;
    }
    __syncthreads();
    tot = red[0];
    float inv = rsqrtf(tot * (1.0f/CDIM) + RMS_EPS);
    y[(size_t)row*CDIM + t] = v * inv * w[t];
}

// ---------------- common GEMM plumbing --------------------------------------
#define PADK 36

__device__ __forceinline__ void cp_async16(void* smem, const void* gmem) {
    unsigned s = (unsigned)__cvta_generic_to_shared(smem);
    asm volatile("cp.async.cg.shared.global [%0], [%1], 16;\n" :: "r"(s), "l"(gmem));
}
#define CP_COMMIT() asm volatile("cp.async.commit_group;\n" ::: "memory")
#define CP_WAIT1()  asm volatile("cp.async.wait_group 1;\n" ::: "memory")
#define CP_WAIT0()  asm volatile("cp.async.wait_group 0;\n" ::: "memory")

#define MMA_TF32(acc, a, b) \
    asm volatile("mma.sync.aligned.m16n8k8.row.col.f32.tf32.tf32.f32 " \
        "{%0,%1,%2,%3}, {%4,%5,%6,%7}, {%8,%9}, {%0,%1,%2,%3};" \
        : "+f"(acc[0]), "+f"(acc[1]), "+f"(acc[2]), "+f"(acc[3]) \
        : "r"(a[0]), "r"(a[1]), "r"(a[2]), "r"(a[3]), "r"(b[0]), "r"(b[1]))

__device__ __forceinline__ void epi_store(float* __restrict__ C, int N,
    const float* __restrict__ bias, const float* __restrict__ res,
    int rr, int col, float v0, float v1, float scale, int mode)
{
    v0 *= scale; v1 *= scale;
    if (mode == 1) {
        v0 += bias[col];   v1 += bias[col+1];
        v0 = 0.5f * v0 * (1.0f + erff(v0 * 0.70710678118654752f));
        v1 = 0.5f * v1 * (1.0f + erff(v1 * 0.70710678118654752f));
    } else if (mode == 2) {
        float u0 = 1.0f + fexp(-v0);
        float u1 = 1.0f + fexp(-v1);
        v0 = flog(fmaf(1e-6f, u0, 1.0f)) - flog(u0);
        v1 = flog(fmaf(1e-6f, u1, 1.0f)) - flog(u1);
    } else {
        if (bias) { v0 += bias[col]; v1 += bias[col+1]; }
        if (res)  { v0 += res[(size_t)rr*N + col]; v1 += res[(size_t)rr*N + col + 1]; }
    }
    *reinterpret_cast<float2*>(&C[(size_t)rr*N + col]) = make_float2(v0, v1);
}

// ---------------- BIG GEMM: BM=64, BN=128, BK=32, 256 thr, warp tile 32x32 --
// z-dim: if B1 != null -> (B,C) = z ? (B1,C1) : (B0,C0); else batch strides.
__global__ __launch_bounds__(256)
void gemm_big(const float* __restrict__ A,
              const float* __restrict__ B0, const float* __restrict__ B1,
              const float* __restrict__ bias, const float* __restrict__ res,
              float* __restrict__ C0, float* __restrict__ C1,
              int N, int K, long sA, long sB, long sC, float scale, int mode)
{
    int z = blockIdx.z;
    const float* B;
    float* C;
    if (B1) { B = z ? B1 : B0; C = z ? C1 : C0; }
    else    { B = B0 + (long)z*sB; C = C0 + (long)z*sC; }
    A += (long)z * sA;

    __shared__ __align__(16) float As[2][64][PADK];
    __shared__ __align__(16) float Bs[2][128][PADK];

    int tid = threadIdx.x;
    int warp = tid >> 5, lane = tid & 31;
    int wm = (warp >> 2) * 32;        // 2 m-warps
    int wn = (warp & 3) * 32;         // 4 n-warps
    int g = lane >> 2, t = lane & 3;
    int m0 = blockIdx.y * 64, n0 = blockIdx.x * 128;

    float acc[2][4][4];
    #pragma unroll
    for (int i = 0; i < 2; ++i)
        #pragma unroll
        for (int j = 0; j < 4; ++j)
            #pragma unroll
            for (int k = 0; k < 4; ++k) acc[i][j][k] = 0.f;

    // stage loader: A 64*8=512 chunks, B 128*8=1024 chunks, 1536/256 = 6 iters
    auto load_stage = [&](int st, int kk) {
        #pragma unroll
        for (int i = 0; i < 6; ++i) {
            int ch = tid + i*256;
            if (ch < 512) {
                int r = ch >> 3, c = (ch & 7) << 2;
                cp_async16(&As[st][r][c], &A[(size_t)(m0 + r)*K + kk + c]);
            } else {
                int ch2 = ch - 512;
                int r = ch2 >> 3, c = (ch2 & 7) << 2;
                cp_async16(&Bs[st][r][c], &B[(size_t)(n0 + r)*K + kk + c]);
            }
        }
    };

    int NIT = K >> 5;
    load_stage(0, 0);
    CP_COMMIT();

    for (int it = 0; it < NIT; ++it) {
        if (it + 1 < NIT) {
            load_stage((it+1)&1, (it+1)*32);
            CP_COMMIT();
            CP_WAIT1();
        } else {
            CP_WAIT0();
        }
        __syncthreads();
        int st = it & 1;
        #pragma unroll
        for (int ks = 0; ks < 4; ++ks) {
            int kb = ks * 8;
            unsigned af[2][4], bf[4][2];
            #pragma unroll
            for (int mt = 0; mt < 2; ++mt) {
                int rr = wm + mt*16;
                af[mt][0] = __float_as_uint(As[st][rr + g    ][kb + t]);
                af[mt][1] = __float_as_uint(As[st][rr + g + 8][kb + t]);
                af[mt][2] = __float_as_uint(As[st][rr + g    ][kb + t + 4]);
                af[mt][3] = __float_as_uint(As[st][rr + g + 8][kb + t + 4]);
            }
            #pragma unroll
            for (int nt = 0; nt < 4; ++nt) {
                int cn = wn + nt*8;
                bf[nt][0] = __float_as_uint(Bs[st][cn + g][kb + t]);
                bf[nt][1] = __float_as_uint(Bs[st][cn + g][kb + t + 4]);
            }
            #pragma unroll
            for (int mt = 0; mt < 2; ++mt)
                #pragma unroll
                for (int nt = 0; nt < 4; ++nt)
                    MMA_TF32(acc[mt][nt], af[mt], bf[nt]);
        }
        __syncthreads();
    }

    #pragma unroll
    for (int mt = 0; mt < 2; ++mt) {
        #pragma unroll
        for (int nt = 0; nt < 4; ++nt) {
            float* cc = acc[mt][nt];
            int row = m0 + wm + mt*16 + g;
            int col = n0 + wn + nt*8 + 2*t;
            #pragma unroll
            for (int hh = 0; hh < 2; ++hh)
                epi_store(C, N, bias, res, row + hh*8, col, cc[hh*2], cc[hh*2+1], scale, mode);
        }
    }
}

// ---------------- small GEMM: BM=32, BN=64, BK=32, 128 thr ------------------
__global__ __launch_bounds__(128)
void gemm_sm(const float* __restrict__ A, const float* __restrict__ B,
             const float* __restrict__ bias, const float* __restrict__ res,
             float* __restrict__ C, int N, int K, float scale, int mode)
{
    __shared__ __align__(16) float As[2][32][PADK];
    __shared__ __align__(16) float Bs[2][64][PADK];

    int tid = threadIdx.x;
    int warp = tid >> 5, lane = tid & 31;
    int wn = warp * 16;               // 4 n-warps, warp tile 32x16
    int g = lane >> 2, t = lane & 3;
    int m0 = blockIdx.y * 32, n0 = blockIdx.x * 64;

    float acc[2][2][4];
    #pragma unroll
    for (int i = 0; i < 2; ++i)
        #pragma unroll
        for (int j = 0; j < 2; ++j)
            #pragma unroll
            for (int k = 0; k < 4; ++k) acc[i][j][k] = 0.f;

    auto load_stage = [&](int st, int kk) {
        #pragma unroll
        for (int i = 0; i < 6; ++i) {       // (32+64)*8 = 768 / 128 = 6
            int ch = tid + i*128;
            if (ch < 256) {
                int r = ch >> 3, c = (ch & 7) << 2;
                cp_async16(&As[st][r][c], &A[(size_t)(m0 + r)*K + kk + c]);
            } else {
                int ch2 = ch - 256;
                int r = ch2 >> 3, c = (ch2 & 7) << 2;
                cp_async16(&Bs[st][r][c], &B[(size_t)(n0 + r)*K + kk + c]);
            }
        }
    };

    int NIT = K >> 5;
    load_stage(0, 0);
    CP_COMMIT();

    for (int it = 0; it < NIT; ++it) {
        if (it + 1 < NIT) {
            load_stage((it+1)&1, (it+1)*32);
            CP_COMMIT();
            CP_WAIT1();
        } else {
            CP_WAIT0();
        }
        __syncthreads();
        int st = it & 1;
        #pragma unroll
        for (int ks = 0; ks < 4; ++ks) {
            int kb = ks * 8;
            unsigned af[2][4], bf[2][2];
            #pragma unroll
            for (int mt = 0; mt < 2; ++mt) {
                int rr = mt*16;
                af[mt][0] = __float_as_uint(As[st][rr + g    ][kb + t]);
                af[mt][1] = __float_as_uint(As[st][rr + g + 8][kb + t]);
                af[mt][2] = __float_as_uint(As[st][rr + g    ][kb + t + 4]);
                af[mt][3] = __float_as_uint(As[st][rr + g + 8][kb + t + 4]);
            }
            #pragma unroll
            for (int nt = 0; nt < 2; ++nt) {
                int cn = wn + nt*8;
                bf[nt][0] = __float_as_uint(Bs[st][cn + g][kb + t]);
                bf[nt][1] = __float_as_uint(Bs[st][cn + g][kb + t + 4]);
            }
            #pragma unroll
            for (int mt = 0; mt < 2; ++mt)
                #pragma unroll
                for (int nt = 0; nt < 2; ++nt)
                    MMA_TF32(acc[mt][nt], af[mt], bf[nt]);
        }
        __syncthreads();
    }

    #pragma unroll
    for (int mt = 0; mt < 2; ++mt) {
        #pragma unroll
        for (int nt = 0; nt < 2; ++nt) {
            float* cc = acc[mt][nt];
            int row = m0 + mt*16 + g;
            int col = n0 + wn + nt*8 + 2*t;
            #pragma unroll
            for (int hh = 0; hh < 2; ++hh)
                epi_store(C, N, bias, res, row + hh*8, col, cc[hh*2], cc[hh*2+1], scale, mode);
        }
    }
}

// ---------------- cross-attention (split-KV flash, block-diagonal) --------
__global__ void cross_attn_partial()
{
    int bh = blockIdx.x;
    int split = blockIdx.y;
    int b = bh >> 3, h = bh & 7;
    int i = threadIdx.x;
    int qi = b*QPER + i;
    const int KS = KVPER / NSPLIT;   // 128
    int j0 = split * KS;

    __shared__ float Ks[32][32];
    __shared__ float Vs[32][32];

    float qreg[DH];
    #pragma unroll
    for (int d = 0; d < DH; ++d) qreg[d] = g_Qc[(size_t)qi*CDIM + h*DH + d];

    float m = -1e30f, l = 0.0f;
    float oacc[DH] = {};
    const float* Kb = g_Kc + (size_t)(b*KVPER + j0)*CDIM + h*DH;
    const float* Vb = g_Vc + (size_t)(b*KVPER + j0)*CDIM + h*DH;
    const float* mb = g_zT + (size_t)b*KVPER*QPER + (size_t)j0*QPER + i;

    for (int jt = 0; jt < KS; jt += 32) {
        __syncthreads();
        for (int idx = i; idx < 1024; idx += 128) {
            int r = idx >> 5, cd = idx & 31;
            Ks[r][cd] = Kb[(size_t)(jt + r)*CDIM + cd];
            Vs[r][cd] = Vb[(size_t)(jt + r)*CDIM + cd];
        }
        __syncthreads();
        for (int j = 0; j < 32; ++j) {
            float s = mb[(size_t)(jt + j)*QPER];
            float s0 = 0.f, s1 = 0.f, s2 = 0.f, s3 = 0.f;
            #pragma unroll
            for (int d = 0; d < DH; d += 4) {
                s0 = fmaf(qreg[d+0], Ks[j][d+0], s0);
                s1 = fmaf(qreg[d+1], Ks[j][d+1], s1);
                s2 = fmaf(qreg[d+2], Ks[j][d+2], s2);
                s3 = fmaf(qreg[d+3], Ks[j][d+3], s3);
            }
            s += (s0 + s1) + (s2 + s3);
            if (s <= m) {
                float p = fexp(s - m);
                l += p;
                #pragma unroll
                for (int d = 0; d < DH; ++d) oacc[d] = fmaf(p, Vs[j][d], oacc[d]);
            } else {
                float corr = fexp(m - s);
                m = s;
                l = fmaf(l, corr, 1.0f);
                #pragma unroll
                for (int d = 0; d < DH; ++d) oacc[d] = fmaf(oacc[d], corr, Vs[j][d]);
            }
        }
    }
    int base = (split*64 + bh)*QPER + i;
    g_pm[base] = m;
    g_pl[base] = l;
    #pragma unroll
    for (int d = 0; d < DH; ++d) g_po[(size_t)base*DH + d] = oacc[d];
}

__global__ void cross_attn_combine()
{
    int qi = blockIdx.x;
    int c = threadIdx.x;
    int h = c >> 5, d = c & 31;
    int b = qi >> 7, i = qi & 127;
    int bh = b*8 + h;
    float mv[NSPLIT], lv[NSPLIT];
    float M = -1e30f;
    #pragma unroll
    for (int s = 0; s < NSPLIT; ++s) {
        int base = (s*64 + bh)*QPER + i;
        mv[s] = g_pm[base];
        lv[s] = g_pl[base];
        M = fmaxf(M, mv[s]);
    }
    float O = 0.f, L = 0.f;
    #pragma unroll
    for (int s = 0; s < NSPLIT; ++s) {
        float w = fexp(mv[s] - M);
        int base = (s*64 + bh)*QPER + i;
        O = fmaf(w, g_po[(size_t)base*DH + d], O);
        L = fmaf(w, lv[s], L);
    }
    g_attn[(size_t)qi*CDIM + c] = O / L;
}

// ---------------- self-attention (block-diagonal 128x128) -----------------
__global__ void self_attn()
{
    int bh = blockIdx.x;
    int b = bh >> 3, h = bh & 7;
    int i = threadIdx.x;
    int qi = b*QPER + i;

    __shared__ float Ks[32][32];
    __shared__ float Vs[32][32];

    float qreg[DH];
    #pragma unroll
    for (int d = 0; d < DH; ++d) qreg[d] = g_Qs[(size_t)qi*CDIM + h*DH + d];

    float m = -1e30f, l = 0.0f;
    float oacc[DH] = {};
    const float* KVb = g_KVs + (size_t)(b*QPER)*(2*CDIM) + h*DH;

    for (int jt = 0; jt < QPER; jt += 32) {
        __syncthreads();
        for (int idx = i; idx < 1024; idx += 128) {
            int r = idx >> 5, cd = idx & 31;
            Ks[r][cd] = KVb[(size_t)(jt + r)*(2*CDIM) + cd];
            Vs[r][cd] = KVb[(size_t)(jt + r)*(2*CDIM) + CDIM + cd];
        }
        __syncthreads();
        for (int j = 0; j < 32; ++j) {
            float s0 = 0.f, s1 = 0.f, s2 = 0.f, s3 = 0.f;
            #pragma unroll
            for (int d = 0; d < DH; d += 4) {
                s0 = fmaf(qreg[d+0], Ks[j][d+0], s0);
                s1 = fmaf(qreg[d+1], Ks[j][d+1], s1);
                s2 = fmaf(qreg[d+2], Ks[j][d+2], s2);
                s3 = fmaf(qreg[d+3], Ks[j][d+3], s3);
            }
            float s = (s0 + s1) + (s2 + s3);
            if (s <= m) {
                float p = fexp(s - m);
                l += p;
                #pragma unroll
                for (int d = 0; d < DH; ++d) oacc[d] = fmaf(p, Vs[j][d], oacc[d]);
            } else {
                float corr = fexp(m - s);
                m = s;
                l = fmaf(l, corr, 1.0f);
                #pragma unroll
                for (int d = 0; d < DH; ++d) oacc[d] = fmaf(oacc[d], corr, Vs[j][d]);
            }
        }
    }
    float inv = 1.0f / l;
    #pragma unroll
    for (int d = 0; d < DH; ++d)
        g_attn[(size_t)qi*CDIM + h*DH + d] = oacc[d] * inv;
}

// ---------------- launch ----------------------------------------------------
static inline float* sym(const void* symbol)
{
    void* p = nullptr;
    cudaGetSymbolAddress(&p, symbol);
    return (float*)p;
}

extern "C" void kernel_launch(void* const* d_in, const int* in_sizes, int n_in,
                              void* d_out, int out_size)
{
    const float* q        = (const float*)d_in[0];
    const float* kv       = (const float*)d_in[1];
    const float* w_norm_kv= (const float*)d_in[4];
    const float* w_norm1  = (const float*)d_in[5];
    const float* w_norm2  = (const float*)d_in[6];
    const float* w_norm3  = (const float*)d_in[7];
    const float* wq_c     = (const float*)d_in[8];
    const float* wk_c     = (const float*)d_in[9];
    const float* wv_c     = (const float*)d_in[10];
    const float* wo_c     = (const float*)d_in[11];
    const float* bo_c     = (const float*)d_in[12];
    const float* wq_s     = (const float*)d_in[13];
    const float* wkv_s    = (const float*)d_in[14];
    const float* wo_s     = (const float*)d_in[15];
    const float* bo_s     = (const float*)d_in[16];
    const float* w1_mlp   = (const float*)d_in[17];
    const float* b1_mlp   = (const float*)d_in[18];
    const float* w2_mlp   = (const float*)d_in[19];
    const float* b2_mlp   = (const float*)d_in[20];
    const float* w1_mask  = (const float*)d_in[21];
    const float* b1_mask  = (const float*)d_in[22];
    const float* w2_mask  = (const float*)d_in[23];
    const float* b2_mask  = (const float*)d_in[24];
    float* out = (float*)d_out;

    float* p_kvn = sym(g_kvn);
    float* p_Kc  = sym(g_Kc);
    float* p_Vc  = sym(g_Vc);
    float* p_mh  = sym(g_mh);
    float* p_mk  = sym(g_mk);
    float* p_zT  = sym(g_zT);
    float* p_qn  = sym(g_qn);
    float* p_Qc  = sym(g_Qc);
    float* p_attn= sym(g_attn);
    float* p_q1  = sym(g_q1);
    float* p_q2  = sym(g_q2);
    float* p_Qs  = sym(g_Qs);
    float* p_KVs = sym(g_KVs);
    float* p_hid = sym(g_hid);

    // 1. kv_n = rms(kv, w_norm_kv)
    rmsnorm_k<<<NKV, CDIM>>>(kv, w_norm_kv, p_kvn);
    // 2-3. mask MLP: mh = gelu(q @ w1_mask^T + b1), mk = mh @ w2_mask^T + b2
    gemm_sm<<<dim3(4,32,1), 128>>>(q,    w1_mask, b1_mask, nullptr, p_mh, CDIM, CDIM, 1.f, 1);
    gemm_sm<<<dim3(4,32,1), 128>>>(p_mh, w2_mask, b2_mask, nullptr, p_mk, CDIM, CDIM, 1.f, 0);
    // 4. zT[b] = log(sigmoid(kv_n[b] @ mk[b]^T)+1e-6)  (big kernel, z = batch)
    gemm_big<<<dim3(1,16,BATCH), 256>>>(p_kvn, p_mk, nullptr, nullptr, nullptr,
                                        p_zT, nullptr, QPER, CDIM,
                                        (long)KVPER*CDIM, (long)QPER*CDIM, (long)KVPER*QPER, 1.f, 2);
    // 5. K & V projections fused in one launch (z selects weight/output)
    gemm_big<<<dim3(2,128,2), 256>>>(p_kvn, wk_c, wv_c, nullptr, nullptr,
                                     p_Kc, p_Vc, CDIM, CDIM, 0, 0, 0, 1.f, 0);
    // 6-7. q_n1, Q projection (scale folded in)
    rmsnorm_k<<<NQ, CDIM>>>(q, w_norm1, p_qn);
    gemm_sm<<<dim3(4,32,1), 128>>>(p_qn, wq_c, nullptr, nullptr, p_Qc, CDIM, CDIM, ATTN_SCALE, 0);
    // 8-9. cross attention
    cross_attn_partial<<<dim3(64, NSPLIT), 128>>>();
    cross_attn_combine<<<NQ, CDIM>>>();
    // 10. q1 = q + attn @ wo_c^T + bo_c
    gemm_sm<<<dim3(4,32,1), 128>>>(p_attn, wo_c, bo_c, q, p_q1, CDIM, CDIM, 1.f, 0);
    // 11-13. self-attn projections
    rmsnorm_k<<<NQ, CDIM>>>(p_q1, w_norm2, p_qn);
    gemm_sm<<<dim3(4,32,1), 128>>>(p_qn, wq_s,  nullptr, nullptr, p_Qs,  CDIM,   CDIM, ATTN_SCALE, 0);
    gemm_sm<<<dim3(8,32,1), 128>>>(p_qn, wkv_s, nullptr, nullptr, p_KVs, 2*CDIM, CDIM, 1.f, 0);
    // 14. self attention
    self_attn<<<64, 128>>>();
    // 15. q2 = q1 + attn @ wo_s^T + bo_s
    gemm_sm<<<dim3(4,32,1), 128>>>(p_attn, wo_s, bo_s, p_q1, p_q2, CDIM, CDIM, 1.f, 0);
    // 16-18. MLP with residual -> out
    rmsnorm_k<<<NQ, CDIM>>>(p_q2, w_norm3, p_qn);
    gemm_big<<<dim3(8,16,1), 256>>>(p_qn, w1_mlp, nullptr, b1_mlp, nullptr,
                                    p_hid, nullptr, 4*CDIM, CDIM, 0, 0, 0, 1.f, 1);
    gemm_sm<<<dim3(4,32,1), 128>>>(p_hid, w2_mlp, b2_mlp, p_q2, out, CDIM, 4*CDIM, 1.f, 0);
}